// round 14
// baseline (speedup 1.0000x reference)
#include <cuda_runtime.h>
#include <cuda_fp16.h>
#include <math.h>
#include <stdint.h>

#define Nn   32
#define Cc   192
#define Tt   256
#define Vv   25
#define Ss   3
#define MID  64
#define TV   6400          /* T*V */
#define C3   576           /* 3*C */
#define KF   1600          /* MID*Vv flattened contraction for attention */

// Scratch (static device arrays; allocation-free per harness rules)
__device__ __align__(16) __half g_xt16[(size_t)Nn * TV * Cc];        // x^T fp16 [n][p][c]
__device__ __align__(16) __half g_win16[C3 * Cc];                    // w_in fp16
__device__ __align__(16) __half g_wff16[Cc * Cc];                    // w_ff fp16
__device__ __align__(16) __half g_qk[(size_t)Nn * 2 * Ss * Tt * KF]; // Q,K fp16 [n][part][s][t][kf]
__device__ __align__(16) __half g_vt16[(size_t)Nn * Ss * KF * Tt];   // V^T fp16 [n][s][j][t]
__device__ __align__(16) __half g_att16[(size_t)Nn * Ss * Tt * Tt];  // att fp16 [ns][t][q]
__device__ __align__(16) __half g_yt16[(size_t)Nn * TV * Cc];        // y^T fp16 [n][p][d]

// ---------------------------------------------------------------------------
// helpers
// ---------------------------------------------------------------------------
__device__ __forceinline__ void mma_f16(float* d, const uint32_t* a,
                                        uint32_t b0, uint32_t b1) {
    asm volatile(
        "mma.sync.aligned.m16n8k16.row.col.f32.f16.f16.f32 "
        "{%0,%1,%2,%3}, {%4,%5,%6,%7}, {%8,%9}, {%0,%1,%2,%3};"
        : "+f"(d[0]), "+f"(d[1]), "+f"(d[2]), "+f"(d[3])
        : "r"(a[0]), "r"(a[1]), "r"(a[2]), "r"(a[3]), "r"(b0), "r"(b1));
}
__device__ __forceinline__ uint32_t smem_u32(const void* p) {
    return (uint32_t)__cvta_generic_to_shared(p);
}
__device__ __forceinline__ void cp16(uint32_t dst, const void* src) {
    asm volatile("cp.async.cg.shared.global [%0], [%1], 16;"
                 :: "r"(dst), "l"(src));
}
#define CP_COMMIT() asm volatile("cp.async.commit_group;")
#define CP_WAITG1() asm volatile("cp.async.wait_group 1;" ::: "memory")

// ---------------------------------------------------------------------------
// fp16 tile format (validated R7-R12): [row][16 halves] = 8 b32/row;
// 16B granule u of row r stored at granule (u ^ ((r>>2)&1)).
// A rows [m][k], B rows [n][k]; warp tile 32m x 64n, BK=16, acc[2][8][4].
// ---------------------------------------------------------------------------
__device__ __forceinline__ void mma16_chunk(const uint32_t* __restrict__ As,
                                            const uint32_t* __restrict__ Bs,
                                            float acc[2][8][4],
                                            int m0, int n0, int g, int ltg) {
    const int xk = 4 * ((g >> 2) & 1);
    const int ka = ltg + xk;
    const int kb = ltg + (xk ^ 4);
    uint32_t a[2][4];
#pragma unroll
    for (int mt = 0; mt < 2; mt++) {
        const uint32_t* Ar = As + (m0 + mt * 16 + g) * 8;
        a[mt][0] = Ar[ka];
        a[mt][1] = Ar[64 + ka];
        a[mt][2] = Ar[kb];
        a[mt][3] = Ar[64 + kb];
    }
#pragma unroll
    for (int nt = 0; nt < 8; nt++) {
        const uint32_t* Br = Bs + (n0 + nt * 8 + g) * 8;
        const uint32_t b0 = Br[ka];
        const uint32_t b1 = Br[kb];
        mma_f16(acc[0][nt], a[0], b0, b1);
        mma_f16(acc[1][nt], a[1], b0, b1);
    }
}
__device__ __forceinline__ int sw_off(int r, int au) {
    return r * 8 + (au ^ ((r >> 2) & 1)) * 4;
}

// ---------------------------------------------------------------------------
// Kernel 0a: weights -> fp16.
// ---------------------------------------------------------------------------
__global__ void k_wcv(const float* __restrict__ w_in,
                      const float* __restrict__ w_ff) {
    const int i = blockIdx.x * 256 + threadIdx.x;
    if (i < C3 * Cc) g_win16[i] = __float2half(w_in[i]);
    if (i < Cc * Cc) g_wff16[i] = __float2half(w_ff[i]);
}

// ---------------------------------------------------------------------------
// Kernel 0b: transpose-convert x [n][c][p] fp32 -> xt16 [n][p][c] fp16.
// ---------------------------------------------------------------------------
__global__ __launch_bounds__(256) void k_cvtx(const float* __restrict__ x) {
    __shared__ uint32_t sm[64 * 97];
    const int n = blockIdx.y, p0 = blockIdx.x * 64;
    const float* xn = x + (size_t)n * Cc * TV;
    for (int idx = threadIdx.x; idx < 96 * 64; idx += 256) {
        const int c2 = idx >> 6, p = idx & 63;
        const float f0 = xn[(size_t)(2 * c2) * TV + p0 + p];
        const float f1 = xn[(size_t)(2 * c2 + 1) * TV + p0 + p];
        const __half2 h = __floats2half2_rn(f0, f1);
        sm[p * 97 + c2] = *(const uint32_t*)&h;
    }
    __syncthreads();
    uint32_t* dst = (uint32_t*)g_xt16 + ((size_t)n * TV + p0) * (Cc / 2);
    for (int idx = threadIdx.x; idx < 64 * 96; idx += 256) {
        const int p = idx / 96, u = idx - p * 96;
        dst[(size_t)p * 96 + u] = sm[p * 97 + u];
    }
}

// ---------------------------------------------------------------------------
// Kernel 1: Q,K projection (fp16 MMA). Block 64(d over Q,K=384 rows) x 256(p).
// ---------------------------------------------------------------------------
__global__ __launch_bounds__(256, 2) void k_qkv(const float* __restrict__ b_in) {
    __shared__ __align__(16) uint32_t As[3][512];
    __shared__ __align__(16) uint32_t Bs[3][2048];
    const int n  = blockIdx.z;
    const int d0 = blockIdx.x * 64;      // 0..320 (Q,K only)
    const int p0 = blockIdx.y * 256;
    const int tid = threadIdx.x, warp = tid >> 5, lane = tid & 31;
    const int wm = warp >> 2, wn = warp & 3;
    const int g = lane >> 2, ltg = lane & 3;

    const int r2 = tid >> 1, au = tid & 1;

    auto stage = [&](int buf, int k0) {
        if (tid < 128)
            cp16(smem_u32(&As[buf][sw_off(r2, au)]),
                 g_win16 + (size_t)(d0 + r2) * Cc + k0 + au * 8);
#pragma unroll
        for (int i = 0; i < 2; i++) {
            const int p = r2 + 128 * i;
            cp16(smem_u32(&Bs[buf][sw_off(p, au)]),
                 g_xt16 + ((size_t)n * TV + p0 + p) * Cc + k0 + au * 8);
        }
    };

    float acc[2][8][4] = {};
    const int NC = Cc / 16;   // 12
    stage(0, 0);  CP_COMMIT();
    stage(1, 16); CP_COMMIT();
#pragma unroll 1
    for (int c = 0; c < NC; c++) {
        CP_WAITG1();
        __syncthreads();
        if (c + 2 < NC) stage((c + 2) % 3, (c + 2) * 16);
        CP_COMMIT();
        mma16_chunk(As[c % 3], Bs[c % 3], acc, wm * 32, wn * 64, g, ltg);
    }

    const int part = d0 / Cc;           // 0=Q, 1=K
    const int s = (d0 % Cc) / MID;
    __half* qk = g_qk + (((size_t)(n * 2 + part) * Ss + s) * Tt) * KF;
#pragma unroll
    for (int mt = 0; mt < 2; mt++)
#pragma unroll
        for (int half = 0; half < 2; half++) {
            const int cch = wm * 32 + mt * 16 + g + half * 8;
            const float bias = b_in[d0 + cch];
#pragma unroll
            for (int nt = 0; nt < 8; nt++)
#pragma unroll
                for (int e = 0; e < 2; e++) {
                    const int p = p0 + wn * 64 + nt * 8 + ltg * 2 + e;
                    const int t = p / 25, v = p - t * 25;
                    qk[(size_t)t * KF + cch * 25 + v] =
                        __float2half(acc[mt][nt][half * 2 + e] + bias);
                }
        }
}

// ---------------------------------------------------------------------------
// Kernel 1b: V projection -> V^T fp16 [j][t], coalesced (R12-proven).
// ---------------------------------------------------------------------------
__global__ __launch_bounds__(256, 2) void k_v(const float* __restrict__ b_in) {
    __shared__ __align__(16) union {
        struct { uint32_t As[3][512]; uint32_t Bs[3][2048]; } p;
        __half vt[64 * 264];
    } sm;
    const int v = blockIdx.x;     // 0..24
    const int s = blockIdx.y;     // 0..2
    const int n = blockIdx.z;
    const int tid = threadIdx.x, warp = tid >> 5, lane = tid & 31;
    const int wm = warp >> 2, wn = warp & 3;
    const int g = lane >> 2, ltg = lane & 3;

    const int wrow = 2 * Cc + s * MID;
    const __half* Wv = g_win16 + (size_t)wrow * Cc;
    const __half* Xt = g_xt16 + (size_t)n * TV * Cc;

    const int r2 = tid >> 1, au = tid & 1;

    auto stage = [&](int buf, int k0) {
        if (tid < 128)
            cp16(smem_u32(&sm.p.As[buf][sw_off(r2, au)]),
                 Wv + (size_t)r2 * Cc + k0 + au * 8);
#pragma unroll
        for (int i = 0; i < 2; i++) {
            const int t = r2 + 128 * i;
            cp16(smem_u32(&sm.p.Bs[buf][sw_off(t, au)]),
                 Xt + (size_t)(25 * t + v) * Cc + k0 + au * 8);
        }
    };

    float acc[2][8][4] = {};
    const int NC = Cc / 16;   // 12
    stage(0, 0);  CP_COMMIT();
    stage(1, 16); CP_COMMIT();
#pragma unroll 1
    for (int c = 0; c < NC; c++) {
        CP_WAITG1();
        __syncthreads();
        if (c + 2 < NC) stage((c + 2) % 3, (c + 2) * 16);
        CP_COMMIT();
        mma16_chunk(sm.p.As[c % 3], sm.p.Bs[c % 3], acc,
                    wm * 32, wn * 64, g, ltg);
    }
    __syncthreads();   // pipeline reads done before aliasing union as vt

#pragma unroll
    for (int mt = 0; mt < 2; mt++)
#pragma unroll
        for (int half = 0; half < 2; half++) {
            const int c = wm * 32 + mt * 16 + g + half * 8;
            const float bias = b_in[wrow + c];
#pragma unroll
            for (int nt = 0; nt < 8; nt++) {
                const int t = wn * 64 + nt * 8 + ltg * 2;
                __half2 hv = __floats2half2_rn(
                    acc[mt][nt][half * 2 + 0] + bias,
                    acc[mt][nt][half * 2 + 1] + bias);
                *(__half2*)&sm.vt[c * 264 + t] = hv;
            }
        }
    __syncthreads();

    __half* vb = g_vt16 + ((size_t)(n * Ss + s) * KF) * Tt;
    for (int idx = tid; idx < 64 * 128; idx += 256) {
        const int c = idx >> 7, w = idx & 127;
        const uint32_t val = *(const uint32_t*)&sm.vt[c * 264 + w * 2];
        ((uint32_t*)(vb + (size_t)(c * 25 + v) * Tt))[w] = val;
    }
}

// ---------------------------------------------------------------------------
// Kernel 2: att = tanh(Q K^T / 1600). fp16 MMA, fp16 output (R12-proven).
// ---------------------------------------------------------------------------
__global__ __launch_bounds__(256, 2) void k_att() {
    __shared__ __align__(16) uint32_t As[3][512];
    __shared__ __align__(16) uint32_t Bs[3][2048];
    const int ns = blockIdx.z;
    const int n = ns / 3, s = ns - 3 * n;
    const int t0 = blockIdx.y * 64;
    const int tid = threadIdx.x, warp = tid >> 5, lane = tid & 31;
    const int wm = warp >> 2, wn = warp & 3;
    const int g = lane >> 2, ltg = lane & 3;

    const __half* Qb = g_qk + (((size_t)(n * 2 + 0) * Ss + s) * Tt) * KF;
    const __half* Kb = g_qk + (((size_t)(n * 2 + 1) * Ss + s) * Tt) * KF;

    const int r2 = tid >> 1, au = tid & 1;

    auto stage = [&](int buf, int k0) {
        if (tid < 128)
            cp16(smem_u32(&As[buf][sw_off(r2, au)]),
                 Qb + (size_t)(t0 + r2) * KF + k0 + au * 8);
#pragma unroll
        for (int i = 0; i < 2; i++) {
            const int q = r2 + 128 * i;
            cp16(smem_u32(&Bs[buf][sw_off(q, au)]),
                 Kb + (size_t)q * KF + k0 + au * 8);
        }
    };

    float acc[2][8][4] = {};
    const int NC = KF / 16;   // 100
    stage(0, 0);  CP_COMMIT();
    stage(1, 16); CP_COMMIT();
#pragma unroll 1
    for (int c = 0; c < NC; c++) {
        CP_WAITG1();
        __syncthreads();
        if (c + 2 < NC) stage((c + 2) % 3, (c + 2) * 16);
        CP_COMMIT();
        mma16_chunk(As[c % 3], Bs[c % 3], acc, wm * 32, wn * 64, g, ltg);
    }

    const float scale = 1.0f / (float)KF;
    __half* arow = g_att16 + (size_t)ns * Tt * Tt;
#pragma unroll
    for (int mt = 0; mt < 2; mt++)
#pragma unroll
        for (int half = 0; half < 2; half++) {
            const int t = t0 + wm * 32 + mt * 16 + g + half * 8;
#pragma unroll
            for (int nt = 0; nt < 8; nt++) {
                const int q = wn * 64 + nt * 8 + ltg * 2;
                __half2 o = __floats2half2_rn(
                    tanhf(acc[mt][nt][half * 2 + 0] * scale),
                    tanhf(acc[mt][nt][half * 2 + 1] * scale));
                *(__half2*)&arow[(size_t)t * Tt + q] = o;
            }
        }
}

// ---------------------------------------------------------------------------
// Kernel 3: y = att @ V, one block per (n,s,v). fp16 MMA.
// M=256(t, 8 warps), N=64(c), K=256(q). A = att16[t][q], B = vt16[c*25+v][q].
// Epilogue: y^T fp16 [p=25t+v][d=s*64+c] — 64 contiguous halves per row.
// ---------------------------------------------------------------------------
__global__ __launch_bounds__(256, 2) void k_y() {
    __shared__ __align__(16) uint32_t As[3][2048];
    __shared__ __align__(16) uint32_t Bs[3][512];
    const int v  = blockIdx.x;    // 0..24
    const int ns = blockIdx.z;
    const int n = ns / 3, s = ns - 3 * n;
    const int tid = threadIdx.x, warp = tid >> 5, lane = tid & 31;
    const int g = lane >> 2, ltg = lane & 3;

    const __half* att = g_att16 + (size_t)ns * Tt * Tt;
    const __half* Vb  = g_vt16 + ((size_t)(n * Ss + s) * KF) * Tt;

    const int r2 = tid >> 1, au = tid & 1;

    auto stage = [&](int buf, int k0) {
#pragma unroll
        for (int i = 0; i < 2; i++) {
            const int t = r2 + 128 * i;
            cp16(smem_u32(&As[buf][sw_off(t, au)]),
                 att + (size_t)t * Tt + k0 + au * 8);
        }
        if (tid < 128)
            cp16(smem_u32(&Bs[buf][sw_off(r2, au)]),
                 Vb + (size_t)(r2 * 25 + v) * Tt + k0 + au * 8);
    };

    float acc[2][8][4] = {};
    const int NC = Tt / 16;   // 16
    stage(0, 0);  CP_COMMIT();
    stage(1, 16); CP_COMMIT();
#pragma unroll 1
    for (int c = 0; c < NC; c++) {
        CP_WAITG1();
        __syncthreads();
        if (c + 2 < NC) stage((c + 2) % 3, (c + 2) * 16);
        CP_COMMIT();
        mma16_chunk(As[c % 3], Bs[c % 3], acc, warp * 32, 0, g, ltg);
    }

    __half* yt = g_yt16 + (size_t)n * TV * Cc + s * MID;
#pragma unroll
    for (int mt = 0; mt < 2; mt++)
#pragma unroll
        for (int half = 0; half < 2; half++) {
            const int t = warp * 32 + mt * 16 + g + half * 8;
            __half* row = yt + (size_t)(t * 25 + v) * Cc;
#pragma unroll
            for (int nt = 0; nt < 8; nt++) {
                const int c = nt * 8 + ltg * 2;
                __half2 hv = __floats2half2_rn(
                    acc[mt][nt][half * 2 + 0],
                    acc[mt][nt][half * 2 + 1]);
                *(__half2*)&row[c] = hv;
            }
        }
}

// ---------------------------------------------------------------------------
// Kernel 4: FF + BN + residual + LeakyReLU, fp16 MMA.
// Block 64(d) x 256(p), K=192. A = wff16[d][c], B = yt16[p][c].
// ---------------------------------------------------------------------------
__global__ __launch_bounds__(256, 2) void k_ff(const float* __restrict__ x,
                                               const float* __restrict__ b_ff,
                                               const float* __restrict__ gamma,
                                               const float* __restrict__ beta,
                                               const float* __restrict__ mean,
                                               const float* __restrict__ var,
                                               float* __restrict__ out) {
    __shared__ __align__(16) uint32_t As[3][512];
    __shared__ __align__(16) uint32_t Bs[3][2048];
    const int n  = blockIdx.z;
    const int d0 = blockIdx.x * 64;
    const int p0 = blockIdx.y * 256;
    const int tid = threadIdx.x, warp = tid >> 5, lane = tid & 31;
    const int wm = warp >> 2, wn = warp & 3;
    const int g = lane >> 2, ltg = lane & 3;

    const __half* yt = g_yt16 + (size_t)n * TV * Cc;

    const int r2 = tid >> 1, au = tid & 1;

    auto stage = [&](int buf, int k0) {
        if (tid < 128)
            cp16(smem_u32(&As[buf][sw_off(r2, au)]),
                 g_wff16 + (size_t)(d0 + r2) * Cc + k0 + au * 8);
#pragma unroll
        for (int i = 0; i < 2; i++) {
            const int p = r2 + 128 * i;
            cp16(smem_u32(&Bs[buf][sw_off(p, au)]),
                 yt + (size_t)(p0 + p) * Cc + k0 + au * 8);
        }
    };

    float acc[2][8][4] = {};
    const int NC = Cc / 16;   // 12
    stage(0, 0);  CP_COMMIT();
    stage(1, 16); CP_COMMIT();
#pragma unroll 1
    for (int c = 0; c < NC; c++) {
        CP_WAITG1();
        __syncthreads();
        if (c + 2 < NC) stage((c + 2) % 3, (c + 2) * 16);
        CP_COMMIT();
        mma16_chunk(As[c % 3], Bs[c % 3], acc, wm * 32, wn * 64, g, ltg);
    }

    const float* xn = x + (size_t)n * Cc * TV;
    float* on = out + (size_t)n * Cc * TV;
#pragma unroll
    for (int mt = 0; mt < 2; mt++)
#pragma unroll
        for (int half = 0; half < 2; half++) {
            const int d = d0 + wm * 32 + mt * 16 + g + half * 8;
            const float inv = gamma[d] * rsqrtf(var[d] + 1e-5f);
            const float add = (b_ff[d] - mean[d]) * inv + beta[d];
#pragma unroll
            for (int nt = 0; nt < 8; nt++) {
                const int p = p0 + wn * 64 + nt * 8 + ltg * 2;
                const size_t off = (size_t)d * TV + p;
                float2 xv = *(const float2*)&xn[off];
                float z0 = xv.x + acc[mt][nt][half * 2 + 0] * inv + add;
                float z1 = xv.y + acc[mt][nt][half * 2 + 1] * inv + add;
                float2 o;
                o.x = z0 >= 0.f ? z0 : 0.1f * z0;
                o.y = z1 >= 0.f ? z1 : 0.1f * z1;
                *(float2*)&on[off] = o;
            }
        }
}

// ---------------------------------------------------------------------------
extern "C" void kernel_launch(void* const* d_in, const int* in_sizes, int n_in,
                              void* d_out, int out_size) {
    (void)in_sizes; (void)n_in; (void)out_size;
    const float* x     = (const float*)d_in[0];
    const float* w_in  = (const float*)d_in[1];
    const float* b_in  = (const float*)d_in[2];
    const float* w_ff  = (const float*)d_in[3];
    const float* b_ff  = (const float*)d_in[4];
    const float* gamma = (const float*)d_in[5];
    const float* beta  = (const float*)d_in[6];
    const float* mean  = (const float*)d_in[7];
    const float* var   = (const float*)d_in[8];
    float* out = (float*)d_out;

    k_wcv <<<(C3 * Cc + 255) / 256, 256>>>(w_in, w_ff);
    k_cvtx<<<dim3(TV / 64, Nn), 256>>>(x);
    k_qkv <<<dim3(2 * Cc / 64, TV / 256, Nn), 256>>>(b_in);
    k_v   <<<dim3(Vv, Ss, Nn), 256>>>(b_in);
    k_att <<<dim3(1, Tt / 64, Nn * Ss), 256>>>();
    k_y   <<<dim3(Vv, 1, Nn * Ss), 256>>>();
    k_ff  <<<dim3(Cc / 64, TV / 256, Nn), 256>>>(x, b_ff, gamma, beta,
                                                 mean, var, out);
}

// round 15
// speedup vs baseline: 1.0388x; 1.0388x over previous
#include <cuda_runtime.h>
#include <cuda_fp16.h>
#include <math.h>
#include <stdint.h>

#define Nn   32
#define Cc   192
#define Tt   256
#define Vv   25
#define Ss   3
#define MID  64
#define TV   6400          /* T*V */
#define C3   576           /* 3*C */
#define KF   1600          /* MID*Vv flattened contraction for attention */

// Scratch (static device arrays; allocation-free per harness rules)
__device__ __align__(16) __half g_xt16[(size_t)Nn * TV * Cc];        // x^T fp16 [n][p][c]
__device__ __align__(16) __half g_win16[C3 * Cc];                    // w_in fp16
__device__ __align__(16) __half g_wff16[Cc * Cc];                    // w_ff fp16
__device__ __align__(16) __half g_qk[(size_t)Nn * 2 * Ss * Tt * KF]; // Q,K fp16 [n][part][s][t][kf]
__device__ __align__(16) __half g_vt16[(size_t)Nn * Ss * KF * Tt];   // V^T fp16 [n][s][j][t]
__device__ __align__(16) __half g_att16[(size_t)Nn * Ss * Tt * Tt];  // att fp16 [ns][t][q]
__device__ __align__(16) __half g_yt16[(size_t)Nn * TV * Cc];        // y^T fp16 [n][p][d]

// ---------------------------------------------------------------------------
// helpers
// ---------------------------------------------------------------------------
__device__ __forceinline__ void mma_f16(float* d, const uint32_t* a,
                                        uint32_t b0, uint32_t b1) {
    asm volatile(
        "mma.sync.aligned.m16n8k16.row.col.f32.f16.f16.f32 "
        "{%0,%1,%2,%3}, {%4,%5,%6,%7}, {%8,%9}, {%0,%1,%2,%3};"
        : "+f"(d[0]), "+f"(d[1]), "+f"(d[2]), "+f"(d[3])
        : "r"(a[0]), "r"(a[1]), "r"(a[2]), "r"(a[3]), "r"(b0), "r"(b1));
}
__device__ __forceinline__ uint32_t smem_u32(const void* p) {
    return (uint32_t)__cvta_generic_to_shared(p);
}
__device__ __forceinline__ void cp16(uint32_t dst, const void* src) {
    asm volatile("cp.async.cg.shared.global [%0], [%1], 16;"
                 :: "r"(dst), "l"(src));
}
#define CP_COMMIT() asm volatile("cp.async.commit_group;")
#define CP_WAITG1() asm volatile("cp.async.wait_group 1;" ::: "memory")

// ---------------------------------------------------------------------------
// fp16 tile format (validated R7-R14): [row][16 halves] = 8 b32/row;
// 16B granule u of row r stored at granule (u ^ ((r>>2)&1)).
// A rows [m][k], B rows [n][k]; warp tile 32m x 64n, BK=16, acc[2][8][4].
// ---------------------------------------------------------------------------
__device__ __forceinline__ void mma16_chunk(const uint32_t* __restrict__ As,
                                            const uint32_t* __restrict__ Bs,
                                            float acc[2][8][4],
                                            int m0, int n0, int g, int ltg) {
    const int xk = 4 * ((g >> 2) & 1);
    const int ka = ltg + xk;
    const int kb = ltg + (xk ^ 4);
    uint32_t a[2][4];
#pragma unroll
    for (int mt = 0; mt < 2; mt++) {
        const uint32_t* Ar = As + (m0 + mt * 16 + g) * 8;
        a[mt][0] = Ar[ka];
        a[mt][1] = Ar[64 + ka];
        a[mt][2] = Ar[kb];
        a[mt][3] = Ar[64 + kb];
    }
#pragma unroll
    for (int nt = 0; nt < 8; nt++) {
        const uint32_t* Br = Bs + (n0 + nt * 8 + g) * 8;
        const uint32_t b0 = Br[ka];
        const uint32_t b1 = Br[kb];
        mma_f16(acc[0][nt], a[0], b0, b1);
        mma_f16(acc[1][nt], a[1], b0, b1);
    }
}
__device__ __forceinline__ int sw_off(int r, int au) {
    return r * 8 + (au ^ ((r >> 2) & 1)) * 4;
}

// Pair-buffer geometry (all GEMMs): 3 pipeline slots, each holds TWO BK=16
// chunks. Total = 3*(PA + PB) b32 where PA/PB are per-pair strides.
#define DYN_B32 15360     /* 3 * (1024 + 4096) = 61440 B */

// ---------------------------------------------------------------------------
// Kernel 0a: weights -> fp16.
// ---------------------------------------------------------------------------
__global__ void k_wcv(const float* __restrict__ w_in,
                      const float* __restrict__ w_ff) {
    const int i = blockIdx.x * 256 + threadIdx.x;
    if (i < C3 * Cc) g_win16[i] = __float2half(w_in[i]);
    if (i < Cc * Cc) g_wff16[i] = __float2half(w_ff[i]);
}

// ---------------------------------------------------------------------------
// Kernel 0b: transpose-convert x [n][c][p] fp32 -> xt16 [n][p][c] fp16.
// ---------------------------------------------------------------------------
__global__ __launch_bounds__(256) void k_cvtx(const float* __restrict__ x) {
    __shared__ uint32_t sm[64 * 97];
    const int n = blockIdx.y, p0 = blockIdx.x * 64;
    const float* xn = x + (size_t)n * Cc * TV;
    for (int idx = threadIdx.x; idx < 96 * 64; idx += 256) {
        const int c2 = idx >> 6, p = idx & 63;
        const float f0 = xn[(size_t)(2 * c2) * TV + p0 + p];
        const float f1 = xn[(size_t)(2 * c2 + 1) * TV + p0 + p];
        const __half2 h = __floats2half2_rn(f0, f1);
        sm[p * 97 + c2] = *(const uint32_t*)&h;
    }
    __syncthreads();
    uint32_t* dst = (uint32_t*)g_xt16 + ((size_t)n * TV + p0) * (Cc / 2);
    for (int idx = threadIdx.x; idx < 64 * 96; idx += 256) {
        const int p = idx / 96, u = idx - p * 96;
        dst[(size_t)p * 96 + u] = sm[p * 97 + u];
    }
}

// ---------------------------------------------------------------------------
// Kernel 1: Q,K projection (fp16 MMA). Block 64(d) x 256(p), K=192.
// Pair-pipelined (BK=32 per slot), 1 sync per pair.
// ---------------------------------------------------------------------------
__global__ __launch_bounds__(256, 2) void k_qkv(const float* __restrict__ b_in) {
    extern __shared__ __align__(16) uint32_t dyn[];
    uint32_t* AsP = dyn;            // 3 x 1024 (pair = 2 x 512)
    uint32_t* BsP = dyn + 3 * 1024; // 3 x 4096 (pair = 2 x 2048)
    const int n  = blockIdx.z;
    const int d0 = blockIdx.x * 64;      // 0..320 (Q,K only)
    const int p0 = blockIdx.y * 256;
    const int tid = threadIdx.x, warp = tid >> 5, lane = tid & 31;
    const int wm = warp >> 2, wn = warp & 3;
    const int g = lane >> 2, ltg = lane & 3;

    const int r2 = tid >> 1, au = tid & 1;

    auto stagepair = [&](int buf, int c2) {
        uint32_t* A0 = AsP + buf * 1024;
        uint32_t* B0 = BsP + buf * 4096;
#pragma unroll
        for (int sub = 0; sub < 2; sub++) {
            const int k0 = c2 * 32 + sub * 16;
            if (tid < 128)
                cp16(smem_u32(A0 + sub * 512 + sw_off(r2, au)),
                     g_win16 + (size_t)(d0 + r2) * Cc + k0 + au * 8);
#pragma unroll
            for (int i = 0; i < 2; i++) {
                const int p = r2 + 128 * i;
                cp16(smem_u32(B0 + sub * 2048 + sw_off(p, au)),
                     g_xt16 + ((size_t)n * TV + p0 + p) * Cc + k0 + au * 8);
            }
        }
    };

    float acc[2][8][4] = {};
    const int NP = Cc / 32;   // 6
    stagepair(0, 0); CP_COMMIT();
    stagepair(1, 1); CP_COMMIT();
#pragma unroll 1
    for (int c2 = 0; c2 < NP; c2++) {
        CP_WAITG1();
        __syncthreads();
        if (c2 + 2 < NP) stagepair((c2 + 2) % 3, c2 + 2);
        CP_COMMIT();
        const int b = c2 % 3;
        mma16_chunk(AsP + b * 1024,       BsP + b * 4096,        acc, wm * 32, wn * 64, g, ltg);
        mma16_chunk(AsP + b * 1024 + 512, BsP + b * 4096 + 2048, acc, wm * 32, wn * 64, g, ltg);
    }

    const int part = d0 / Cc;           // 0=Q, 1=K
    const int s = (d0 % Cc) / MID;
    __half* qk = g_qk + (((size_t)(n * 2 + part) * Ss + s) * Tt) * KF;
#pragma unroll
    for (int mt = 0; mt < 2; mt++)
#pragma unroll
        for (int half = 0; half < 2; half++) {
            const int cch = wm * 32 + mt * 16 + g + half * 8;
            const float bias = b_in[d0 + cch];
#pragma unroll
            for (int nt = 0; nt < 8; nt++)
#pragma unroll
                for (int e = 0; e < 2; e++) {
                    const int p = p0 + wn * 64 + nt * 8 + ltg * 2 + e;
                    const int t = p / 25, v = p - t * 25;
                    qk[(size_t)t * KF + cch * 25 + v] =
                        __float2half(acc[mt][nt][half * 2 + e] + bias);
                }
        }
}

// ---------------------------------------------------------------------------
// Kernel 1b: V projection -> V^T fp16 [j][t], coalesced. Pair-pipelined.
// ---------------------------------------------------------------------------
__global__ __launch_bounds__(256, 2) void k_v(const float* __restrict__ b_in) {
    extern __shared__ __align__(16) uint32_t dyn[];
    uint32_t* AsP = dyn;
    uint32_t* BsP = dyn + 3 * 1024;
    __half*  vt  = (__half*)dyn;    // epilogue alias (64 x 264 halves = 33 KB)
    const int v = blockIdx.x;     // 0..24
    const int s = blockIdx.y;     // 0..2
    const int n = blockIdx.z;
    const int tid = threadIdx.x, warp = tid >> 5, lane = tid & 31;
    const int wm = warp >> 2, wn = warp & 3;
    const int g = lane >> 2, ltg = lane & 3;

    const int wrow = 2 * Cc + s * MID;
    const __half* Wv = g_win16 + (size_t)wrow * Cc;
    const __half* Xt = g_xt16 + (size_t)n * TV * Cc;

    const int r2 = tid >> 1, au = tid & 1;

    auto stagepair = [&](int buf, int c2) {
        uint32_t* A0 = AsP + buf * 1024;
        uint32_t* B0 = BsP + buf * 4096;
#pragma unroll
        for (int sub = 0; sub < 2; sub++) {
            const int k0 = c2 * 32 + sub * 16;
            if (tid < 128)
                cp16(smem_u32(A0 + sub * 512 + sw_off(r2, au)),
                     Wv + (size_t)r2 * Cc + k0 + au * 8);
#pragma unroll
            for (int i = 0; i < 2; i++) {
                const int t = r2 + 128 * i;
                cp16(smem_u32(B0 + sub * 2048 + sw_off(t, au)),
                     Xt + (size_t)(25 * t + v) * Cc + k0 + au * 8);
            }
        }
    };

    float acc[2][8][4] = {};
    const int NP = Cc / 32;   // 6
    stagepair(0, 0); CP_COMMIT();
    stagepair(1, 1); CP_COMMIT();
#pragma unroll 1
    for (int c2 = 0; c2 < NP; c2++) {
        CP_WAITG1();
        __syncthreads();
        if (c2 + 2 < NP) stagepair((c2 + 2) % 3, c2 + 2);
        CP_COMMIT();
        const int b = c2 % 3;
        mma16_chunk(AsP + b * 1024,       BsP + b * 4096,        acc, wm * 32, wn * 64, g, ltg);
        mma16_chunk(AsP + b * 1024 + 512, BsP + b * 4096 + 2048, acc, wm * 32, wn * 64, g, ltg);
    }
    __syncthreads();   // pipeline reads done before aliasing dyn as vt

#pragma unroll
    for (int mt = 0; mt < 2; mt++)
#pragma unroll
        for (int half = 0; half < 2; half++) {
            const int c = wm * 32 + mt * 16 + g + half * 8;
            const float bias = b_in[wrow + c];
#pragma unroll
            for (int nt = 0; nt < 8; nt++) {
                const int t = wn * 64 + nt * 8 + ltg * 2;
                __half2 hv = __floats2half2_rn(
                    acc[mt][nt][half * 2 + 0] + bias,
                    acc[mt][nt][half * 2 + 1] + bias);
                *(__half2*)&vt[c * 264 + t] = hv;
            }
        }
    __syncthreads();

    __half* vb = g_vt16 + ((size_t)(n * Ss + s) * KF) * Tt;
    for (int idx = tid; idx < 64 * 128; idx += 256) {
        const int c = idx >> 7, w = idx & 127;
        const uint32_t val = *(const uint32_t*)&vt[c * 264 + w * 2];
        ((uint32_t*)(vb + (size_t)(c * 25 + v) * Tt))[w] = val;
    }
}

// ---------------------------------------------------------------------------
// Kernel 2: att = tanh(Q K^T / 1600). fp16 MMA, fp16 output. Pair-pipelined
// (K=1600 -> 50 pairs; barrier count halved vs R14).
// ---------------------------------------------------------------------------
__global__ __launch_bounds__(256, 2) void k_att() {
    extern __shared__ __align__(16) uint32_t dyn[];
    uint32_t* AsP = dyn;
    uint32_t* BsP = dyn + 3 * 1024;
    const int ns = blockIdx.z;
    const int n = ns / 3, s = ns - 3 * n;
    const int t0 = blockIdx.y * 64;
    const int tid = threadIdx.x, warp = tid >> 5, lane = tid & 31;
    const int wm = warp >> 2, wn = warp & 3;
    const int g = lane >> 2, ltg = lane & 3;

    const __half* Qb = g_qk + (((size_t)(n * 2 + 0) * Ss + s) * Tt) * KF;
    const __half* Kb = g_qk + (((size_t)(n * 2 + 1) * Ss + s) * Tt) * KF;

    const int r2 = tid >> 1, au = tid & 1;

    auto stagepair = [&](int buf, int c2) {
        uint32_t* A0 = AsP + buf * 1024;
        uint32_t* B0 = BsP + buf * 4096;
#pragma unroll
        for (int sub = 0; sub < 2; sub++) {
            const int k0 = c2 * 32 + sub * 16;
            if (tid < 128)
                cp16(smem_u32(A0 + sub * 512 + sw_off(r2, au)),
                     Qb + (size_t)(t0 + r2) * KF + k0 + au * 8);
#pragma unroll
            for (int i = 0; i < 2; i++) {
                const int q = r2 + 128 * i;
                cp16(smem_u32(B0 + sub * 2048 + sw_off(q, au)),
                     Kb + (size_t)q * KF + k0 + au * 8);
            }
        }
    };

    float acc[2][8][4] = {};
    const int NP = KF / 32;   // 50
    stagepair(0, 0); CP_COMMIT();
    stagepair(1, 1); CP_COMMIT();
#pragma unroll 1
    for (int c2 = 0; c2 < NP; c2++) {
        CP_WAITG1();
        __syncthreads();
        if (c2 + 2 < NP) stagepair((c2 + 2) % 3, c2 + 2);
        CP_COMMIT();
        const int b = c2 % 3;
        mma16_chunk(AsP + b * 1024,       BsP + b * 4096,        acc, wm * 32, wn * 64, g, ltg);
        mma16_chunk(AsP + b * 1024 + 512, BsP + b * 4096 + 2048, acc, wm * 32, wn * 64, g, ltg);
    }

    const float scale = 1.0f / (float)KF;
    __half* arow = g_att16 + (size_t)ns * Tt * Tt;
#pragma unroll
    for (int mt = 0; mt < 2; mt++)
#pragma unroll
        for (int half = 0; half < 2; half++) {
            const int t = t0 + wm * 32 + mt * 16 + g + half * 8;
#pragma unroll
            for (int nt = 0; nt < 8; nt++) {
                const int q = wn * 64 + nt * 8 + ltg * 2;
                __half2 o = __floats2half2_rn(
                    tanhf(acc[mt][nt][half * 2 + 0] * scale),
                    tanhf(acc[mt][nt][half * 2 + 1] * scale));
                *(__half2*)&arow[(size_t)t * Tt + q] = o;
            }
        }
}

// ---------------------------------------------------------------------------
// Kernel 3: y = att @ V, one block per (n,s,v). fp16 MMA. Pair-pipelined.
// M=256(t, 8 warps), N=64(c), K=256(q). Epilogue: y^T fp16 [p][d].
// ---------------------------------------------------------------------------
__global__ __launch_bounds__(256, 2) void k_y() {
    extern __shared__ __align__(16) uint32_t dyn[];
    uint32_t* AsP = dyn;            // 3 x 4096 (pair = 2 x 2048)
    uint32_t* BsP = dyn + 3 * 4096; // 3 x 1024 (pair = 2 x 512)
    const int v  = blockIdx.x;    // 0..24
    const int ns = blockIdx.z;
    const int n = ns / 3, s = ns - 3 * n;
    const int tid = threadIdx.x, warp = tid >> 5, lane = tid & 31;
    const int g = lane >> 2, ltg = lane & 3;

    const __half* att = g_att16 + (size_t)ns * Tt * Tt;
    const __half* Vb  = g_vt16 + ((size_t)(n * Ss + s) * KF) * Tt;

    const int r2 = tid >> 1, au = tid & 1;

    auto stagepair = [&](int buf, int c2) {
        uint32_t* A0 = AsP + buf * 4096;
        uint32_t* B0 = BsP + buf * 1024;
#pragma unroll
        for (int sub = 0; sub < 2; sub++) {
            const int k0 = c2 * 32 + sub * 16;
#pragma unroll
            for (int i = 0; i < 2; i++) {
                const int t = r2 + 128 * i;
                cp16(smem_u32(A0 + sub * 2048 + sw_off(t, au)),
                     att + (size_t)t * Tt + k0 + au * 8);
            }
            if (tid < 128)
                cp16(smem_u32(B0 + sub * 512 + sw_off(r2, au)),
                     Vb + (size_t)(r2 * 25 + v) * Tt + k0 + au * 8);
        }
    };

    float acc[2][8][4] = {};
    const int NP = Tt / 32;   // 8
    stagepair(0, 0); CP_COMMIT();
    stagepair(1, 1); CP_COMMIT();
#pragma unroll 1
    for (int c2 = 0; c2 < NP; c2++) {
        CP_WAITG1();
        __syncthreads();
        if (c2 + 2 < NP) stagepair((c2 + 2) % 3, c2 + 2);
        CP_COMMIT();
        const int b = c2 % 3;
        mma16_chunk(AsP + b * 4096,        BsP + b * 1024,       acc, warp * 32, 0, g, ltg);
        mma16_chunk(AsP + b * 4096 + 2048, BsP + b * 1024 + 512, acc, warp * 32, 0, g, ltg);
    }

    __half* yt = g_yt16 + (size_t)n * TV * Cc + s * MID;
#pragma unroll
    for (int mt = 0; mt < 2; mt++)
#pragma unroll
        for (int half = 0; half < 2; half++) {
            const int t = warp * 32 + mt * 16 + g + half * 8;
            __half* row = yt + (size_t)(t * 25 + v) * Cc;
#pragma unroll
            for (int nt = 0; nt < 8; nt++) {
                const int c = nt * 8 + ltg * 2;
                __half2 hv = __floats2half2_rn(
                    acc[mt][nt][half * 2 + 0],
                    acc[mt][nt][half * 2 + 1]);
                *(__half2*)&row[c] = hv;
            }
        }
}

// ---------------------------------------------------------------------------
// Kernel 4: FF + BN + residual + LeakyReLU, fp16 MMA. Pair-pipelined.
// ---------------------------------------------------------------------------
__global__ __launch_bounds__(256, 2) void k_ff(const float* __restrict__ x,
                                               const float* __restrict__ b_ff,
                                               const float* __restrict__ gamma,
                                               const float* __restrict__ beta,
                                               const float* __restrict__ mean,
                                               const float* __restrict__ var,
                                               float* __restrict__ out) {
    extern __shared__ __align__(16) uint32_t dyn[];
    uint32_t* AsP = dyn;
    uint32_t* BsP = dyn + 3 * 1024;
    const int n  = blockIdx.z;
    const int d0 = blockIdx.x * 64;
    const int p0 = blockIdx.y * 256;
    const int tid = threadIdx.x, warp = tid >> 5, lane = tid & 31;
    const int wm = warp >> 2, wn = warp & 3;
    const int g = lane >> 2, ltg = lane & 3;

    const __half* yt = g_yt16 + (size_t)n * TV * Cc;

    const int r2 = tid >> 1, au = tid & 1;

    auto stagepair = [&](int buf, int c2) {
        uint32_t* A0 = AsP + buf * 1024;
        uint32_t* B0 = BsP + buf * 4096;
#pragma unroll
        for (int sub = 0; sub < 2; sub++) {
            const int k0 = c2 * 32 + sub * 16;
            if (tid < 128)
                cp16(smem_u32(A0 + sub * 512 + sw_off(r2, au)),
                     g_wff16 + (size_t)(d0 + r2) * Cc + k0 + au * 8);
#pragma unroll
            for (int i = 0; i < 2; i++) {
                const int p = r2 + 128 * i;
                cp16(smem_u32(B0 + sub * 2048 + sw_off(p, au)),
                     yt + (size_t)(p0 + p) * Cc + k0 + au * 8);
            }
        }
    };

    float acc[2][8][4] = {};
    const int NP = Cc / 32;   // 6
    stagepair(0, 0); CP_COMMIT();
    stagepair(1, 1); CP_COMMIT();
#pragma unroll 1
    for (int c2 = 0; c2 < NP; c2++) {
        CP_WAITG1();
        __syncthreads();
        if (c2 + 2 < NP) stagepair((c2 + 2) % 3, c2 + 2);
        CP_COMMIT();
        const int b = c2 % 3;
        mma16_chunk(AsP + b * 1024,       BsP + b * 4096,        acc, wm * 32, wn * 64, g, ltg);
        mma16_chunk(AsP + b * 1024 + 512, BsP + b * 4096 + 2048, acc, wm * 32, wn * 64, g, ltg);
    }

    const float* xn = x + (size_t)n * Cc * TV;
    float* on = out + (size_t)n * Cc * TV;
#pragma unroll
    for (int mt = 0; mt < 2; mt++)
#pragma unroll
        for (int half = 0; half < 2; half++) {
            const int d = d0 + wm * 32 + mt * 16 + g + half * 8;
            const float inv = gamma[d] * rsqrtf(var[d] + 1e-5f);
            const float add = (b_ff[d] - mean[d]) * inv + beta[d];
#pragma unroll
            for (int nt = 0; nt < 8; nt++) {
                const int p = p0 + wn * 64 + nt * 8 + ltg * 2;
                const size_t off = (size_t)d * TV + p;
                float2 xv = *(const float2*)&xn[off];
                float z0 = xv.x + acc[mt][nt][half * 2 + 0] * inv + add;
                float z1 = xv.y + acc[mt][nt][half * 2 + 1] * inv + add;
                float2 o;
                o.x = z0 >= 0.f ? z0 : 0.1f * z0;
                o.y = z1 >= 0.f ? z1 : 0.1f * z1;
                *(float2*)&on[off] = o;
            }
        }
}

// ---------------------------------------------------------------------------
extern "C" void kernel_launch(void* const* d_in, const int* in_sizes, int n_in,
                              void* d_out, int out_size) {
    (void)in_sizes; (void)n_in; (void)out_size;
    const float* x     = (const float*)d_in[0];
    const float* w_in  = (const float*)d_in[1];
    const float* b_in  = (const float*)d_in[2];
    const float* w_ff  = (const float*)d_in[3];
    const float* b_ff  = (const float*)d_in[4];
    const float* gamma = (const float*)d_in[5];
    const float* beta  = (const float*)d_in[6];
    const float* mean  = (const float*)d_in[7];
    const float* var   = (const float*)d_in[8];
    float* out = (float*)d_out;

    const int SM = DYN_B32 * 4;   // 61440 B
    static bool attr_set = false;
    if (!attr_set) {
        cudaFuncSetAttribute(k_qkv, cudaFuncAttributeMaxDynamicSharedMemorySize, SM);
        cudaFuncSetAttribute(k_v,   cudaFuncAttributeMaxDynamicSharedMemorySize, SM);
        cudaFuncSetAttribute(k_att, cudaFuncAttributeMaxDynamicSharedMemorySize, SM);
        cudaFuncSetAttribute(k_y,   cudaFuncAttributeMaxDynamicSharedMemorySize, SM);
        cudaFuncSetAttribute(k_ff,  cudaFuncAttributeMaxDynamicSharedMemorySize, SM);
        attr_set = true;
    }

    k_wcv <<<(C3 * Cc + 255) / 256, 256>>>(w_in, w_ff);
    k_cvtx<<<dim3(TV / 64, Nn), 256>>>(x);
    k_qkv <<<dim3(2 * Cc / 64, TV / 256, Nn), 256, SM>>>(b_in);
    k_v   <<<dim3(Vv, Ss, Nn), 256, SM>>>(b_in);
    k_att <<<dim3(1, Tt / 64, Nn * Ss), 256, SM>>>();
    k_y   <<<dim3(Vv, 1, Nn * Ss), 256, SM>>>();
    k_ff  <<<dim3(Cc / 64, TV / 256, Nn), 256, SM>>>(x, b_ff, gamma, beta,
                                                     mean, var, out);
}

// round 16
// speedup vs baseline: 1.0906x; 1.0499x over previous
#include <cuda_runtime.h>
#include <cuda_fp16.h>
#include <math.h>
#include <stdint.h>

#define Nn   32
#define Cc   192
#define Tt   256
#define Vv   25
#define Ss   3
#define MID  64
#define TV   6400          /* T*V */
#define C3   576           /* 3*C */
#define KF   1600          /* MID*Vv flattened contraction for attention */

// Scratch (static device arrays; allocation-free per harness rules)
__device__ __align__(16) __half g_xt16[(size_t)Nn * TV * Cc];        // x^T fp16 [n][p][c]
__device__ __align__(16) __half g_win16[C3 * Cc];                    // w_in fp16
__device__ __align__(16) __half g_wff16[Cc * Cc];                    // w_ff fp16
__device__ __align__(16) __half g_qk[(size_t)Nn * 2 * Ss * Tt * KF]; // Q,K fp16 [n][part][s][t][kf]
__device__ __align__(16) __half g_vt16[(size_t)Nn * Ss * KF * Tt];   // V^T fp16 [n][s][j][t]
__device__ __align__(16) __half g_att16[(size_t)Nn * Ss * Tt * Tt];  // att fp16 [ns][t][q]
__device__ __align__(16) __half g_yt16[(size_t)Nn * TV * Cc];        // y^T fp16 [n][p][d]

// ---------------------------------------------------------------------------
// helpers
// ---------------------------------------------------------------------------
__device__ __forceinline__ void mma_f16(float* d, const uint32_t* a,
                                        uint32_t b0, uint32_t b1) {
    asm volatile(
        "mma.sync.aligned.m16n8k16.row.col.f32.f16.f16.f32 "
        "{%0,%1,%2,%3}, {%4,%5,%6,%7}, {%8,%9}, {%0,%1,%2,%3};"
        : "+f"(d[0]), "+f"(d[1]), "+f"(d[2]), "+f"(d[3])
        : "r"(a[0]), "r"(a[1]), "r"(a[2]), "r"(a[3]), "r"(b0), "r"(b1));
}
__device__ __forceinline__ void ldsm4(uint32_t* r, uint32_t addr) {
    asm volatile(
        "ldmatrix.sync.aligned.m8n8.x4.shared.b16 {%0,%1,%2,%3}, [%4];"
        : "=r"(r[0]), "=r"(r[1]), "=r"(r[2]), "=r"(r[3]) : "r"(addr));
}
__device__ __forceinline__ uint32_t smem_u32(const void* p) {
    return (uint32_t)__cvta_generic_to_shared(p);
}
__device__ __forceinline__ void cp16(uint32_t dst, const void* src) {
    asm volatile("cp.async.cg.shared.global [%0], [%1], 16;"
                 :: "r"(dst), "l"(src));
}
#define CP_COMMIT() asm volatile("cp.async.commit_group;")
#define CP_WAITG1() asm volatile("cp.async.wait_group 1;" ::: "memory")

// ---------------------------------------------------------------------------
// fp16 tile format (validated R7-R15): [row][16 halves] = 8 b32/row;
// 16B granule u of row r stored at granule (u ^ ((r>>2)&1)).
// Fragment loads now via ldmatrix.x4 (same layout, verified conflict-free):
//   A x4 tiles: (m0-7,k0-7)(m8-15,k0-7)(m0-7,k8-15)(m8-15,k8-15) = a0..a3
//   B x4 tiles: (nA,k0)(nA,k1)(nB,k0)(nB,k1) non-trans on [n][k] rows.
// Per-thread byte offsets are loop-invariant -> precomputed.
// ---------------------------------------------------------------------------
__device__ __forceinline__ void frag_offsets(int m0, int n0, int lane,
                                             uint32_t aoff[2], uint32_t boff[4]) {
#pragma unroll
    for (int mt = 0; mt < 2; mt++) {
        const int row = m0 + mt * 16 + (lane & 15);
        const int kh = lane >> 4;
        const int gr = kh ^ ((row >> 2) & 1);
        aoff[mt] = (uint32_t)(row * 8 + gr * 4) * 4;
    }
#pragma unroll
    for (int np = 0; np < 4; np++) {
        const int row = n0 + np * 16 + ((lane >> 4) << 3) + (lane & 7);
        const int kh = (lane >> 3) & 1;
        const int gr = kh ^ ((row >> 2) & 1);
        boff[np] = (uint32_t)(row * 8 + gr * 4) * 4;
    }
}

__device__ __forceinline__ void mma16_ldsm(uint32_t Abase, uint32_t Bbase,
                                           const uint32_t* aoff,
                                           const uint32_t* boff,
                                           float acc[2][8][4]) {
    uint32_t a[2][4];
    ldsm4(a[0], Abase + aoff[0]);
    ldsm4(a[1], Abase + aoff[1]);
#pragma unroll
    for (int np = 0; np < 4; np++) {
        uint32_t b4[4];
        ldsm4(b4, Bbase + boff[np]);
        mma_f16(acc[0][2 * np],     a[0], b4[0], b4[1]);
        mma_f16(acc[1][2 * np],     a[1], b4[0], b4[1]);
        mma_f16(acc[0][2 * np + 1], a[0], b4[2], b4[3]);
        mma_f16(acc[1][2 * np + 1], a[1], b4[2], b4[3]);
    }
}

__device__ __forceinline__ int sw_off(int r, int au) {
    return r * 8 + (au ^ ((r >> 2) & 1)) * 4;
}

// Pair-buffer geometry: 3 pipeline slots x two BK=16 chunks.
#define DYN_B32 15360     /* 3 * (1024 + 4096) = 61440 B */

// ---------------------------------------------------------------------------
// Kernel 0a: weights -> fp16.
// ---------------------------------------------------------------------------
__global__ void k_wcv(const float* __restrict__ w_in,
                      const float* __restrict__ w_ff) {
    const int i = blockIdx.x * 256 + threadIdx.x;
    if (i < C3 * Cc) g_win16[i] = __float2half(w_in[i]);
    if (i < Cc * Cc) g_wff16[i] = __float2half(w_ff[i]);
}

// ---------------------------------------------------------------------------
// Kernel 0b: transpose-convert x [n][c][p] fp32 -> xt16 [n][p][c] fp16.
// ---------------------------------------------------------------------------
__global__ __launch_bounds__(256) void k_cvtx(const float* __restrict__ x) {
    __shared__ uint32_t sm[64 * 97];
    const int n = blockIdx.y, p0 = blockIdx.x * 64;
    const float* xn = x + (size_t)n * Cc * TV;
    for (int idx = threadIdx.x; idx < 96 * 64; idx += 256) {
        const int c2 = idx >> 6, p = idx & 63;
        const float f0 = xn[(size_t)(2 * c2) * TV + p0 + p];
        const float f1 = xn[(size_t)(2 * c2 + 1) * TV + p0 + p];
        const __half2 h = __floats2half2_rn(f0, f1);
        sm[p * 97 + c2] = *(const uint32_t*)&h;
    }
    __syncthreads();
    uint32_t* dst = (uint32_t*)g_xt16 + ((size_t)n * TV + p0) * (Cc / 2);
    for (int idx = threadIdx.x; idx < 64 * 96; idx += 256) {
        const int p = idx / 96, u = idx - p * 96;
        dst[(size_t)p * 96 + u] = sm[p * 97 + u];
    }
}

// ---------------------------------------------------------------------------
// Kernel 1: Q,K projection (fp16 MMA + ldmatrix). Block 64(d) x 256(p), K=192.
// ---------------------------------------------------------------------------
__global__ __launch_bounds__(256, 2) void k_qkv(const float* __restrict__ b_in) {
    extern __shared__ __align__(16) uint32_t dyn[];
    uint32_t* AsP = dyn;            // 3 x 1024 (pair = 2 x 512)
    uint32_t* BsP = dyn + 3 * 1024; // 3 x 4096 (pair = 2 x 2048)
    const int n  = blockIdx.z;
    const int d0 = blockIdx.x * 64;      // 0..320 (Q,K only)
    const int p0 = blockIdx.y * 256;
    const int tid = threadIdx.x, warp = tid >> 5, lane = tid & 31;
    const int wm = warp >> 2, wn = warp & 3;
    const int g = lane >> 2, ltg = lane & 3;

    const int r2 = tid >> 1, au = tid & 1;

    uint32_t aoff[2], boff[4];
    frag_offsets(wm * 32, wn * 64, lane, aoff, boff);
    uint32_t Ab[3], Bb[3];
#pragma unroll
    for (int s2 = 0; s2 < 3; s2++) {
        Ab[s2] = smem_u32(AsP + s2 * 1024);
        Bb[s2] = smem_u32(BsP + s2 * 4096);
    }

    auto stagepair = [&](int buf, int c2) {
        uint32_t* A0 = AsP + buf * 1024;
        uint32_t* B0 = BsP + buf * 4096;
#pragma unroll
        for (int sub = 0; sub < 2; sub++) {
            const int k0 = c2 * 32 + sub * 16;
            if (tid < 128)
                cp16(smem_u32(A0 + sub * 512 + sw_off(r2, au)),
                     g_win16 + (size_t)(d0 + r2) * Cc + k0 + au * 8);
#pragma unroll
            for (int i = 0; i < 2; i++) {
                const int p = r2 + 128 * i;
                cp16(smem_u32(B0 + sub * 2048 + sw_off(p, au)),
                     g_xt16 + ((size_t)n * TV + p0 + p) * Cc + k0 + au * 8);
            }
        }
    };

    float acc[2][8][4] = {};
    const int NP = Cc / 32;   // 6
    stagepair(0, 0); CP_COMMIT();
    stagepair(1, 1); CP_COMMIT();
#pragma unroll 1
    for (int c2 = 0; c2 < NP; c2++) {
        CP_WAITG1();
        __syncthreads();
        if (c2 + 2 < NP) stagepair((c2 + 2) % 3, c2 + 2);
        CP_COMMIT();
        const int b = c2 % 3;
        mma16_ldsm(Ab[b],            Bb[b],            aoff, boff, acc);
        mma16_ldsm(Ab[b] + 512 * 4,  Bb[b] + 2048 * 4, aoff, boff, acc);
    }

    const int part = d0 / Cc;           // 0=Q, 1=K
    const int s = (d0 % Cc) / MID;
    __half* qk = g_qk + (((size_t)(n * 2 + part) * Ss + s) * Tt) * KF;
#pragma unroll
    for (int mt = 0; mt < 2; mt++)
#pragma unroll
        for (int half = 0; half < 2; half++) {
            const int cch = wm * 32 + mt * 16 + g + half * 8;
            const float bias = b_in[d0 + cch];
#pragma unroll
            for (int nt = 0; nt < 8; nt++)
#pragma unroll
                for (int e = 0; e < 2; e++) {
                    const int p = p0 + wn * 64 + nt * 8 + ltg * 2 + e;
                    const int t = p / 25, v = p - t * 25;
                    qk[(size_t)t * KF + cch * 25 + v] =
                        __float2half(acc[mt][nt][half * 2 + e] + bias);
                }
        }
}

// ---------------------------------------------------------------------------
// Kernel 1b: V projection -> V^T fp16 [j][t], coalesced. ldmatrix fragments.
// ---------------------------------------------------------------------------
__global__ __launch_bounds__(256, 2) void k_v(const float* __restrict__ b_in) {
    extern __shared__ __align__(16) uint32_t dyn[];
    uint32_t* AsP = dyn;
    uint32_t* BsP = dyn + 3 * 1024;
    __half*  vt  = (__half*)dyn;    // epilogue alias (64 x 264 halves = 33 KB)
    const int v = blockIdx.x;     // 0..24
    const int s = blockIdx.y;     // 0..2
    const int n = blockIdx.z;
    const int tid = threadIdx.x, warp = tid >> 5, lane = tid & 31;
    const int wm = warp >> 2, wn = warp & 3;
    const int g = lane >> 2, ltg = lane & 3;

    const int wrow = 2 * Cc + s * MID;
    const __half* Wv = g_win16 + (size_t)wrow * Cc;
    const __half* Xt = g_xt16 + (size_t)n * TV * Cc;

    const int r2 = tid >> 1, au = tid & 1;

    uint32_t aoff[2], boff[4];
    frag_offsets(wm * 32, wn * 64, lane, aoff, boff);
    uint32_t Ab[3], Bb[3];
#pragma unroll
    for (int s2 = 0; s2 < 3; s2++) {
        Ab[s2] = smem_u32(AsP + s2 * 1024);
        Bb[s2] = smem_u32(BsP + s2 * 4096);
    }

    auto stagepair = [&](int buf, int c2) {
        uint32_t* A0 = AsP + buf * 1024;
        uint32_t* B0 = BsP + buf * 4096;
#pragma unroll
        for (int sub = 0; sub < 2; sub++) {
            const int k0 = c2 * 32 + sub * 16;
            if (tid < 128)
                cp16(smem_u32(A0 + sub * 512 + sw_off(r2, au)),
                     Wv + (size_t)r2 * Cc + k0 + au * 8);
#pragma unroll
            for (int i = 0; i < 2; i++) {
                const int t = r2 + 128 * i;
                cp16(smem_u32(B0 + sub * 2048 + sw_off(t, au)),
                     Xt + (size_t)(25 * t + v) * Cc + k0 + au * 8);
            }
        }
    };

    float acc[2][8][4] = {};
    const int NP = Cc / 32;   // 6
    stagepair(0, 0); CP_COMMIT();
    stagepair(1, 1); CP_COMMIT();
#pragma unroll 1
    for (int c2 = 0; c2 < NP; c2++) {
        CP_WAITG1();
        __syncthreads();
        if (c2 + 2 < NP) stagepair((c2 + 2) % 3, c2 + 2);
        CP_COMMIT();
        const int b = c2 % 3;
        mma16_ldsm(Ab[b],           Bb[b],            aoff, boff, acc);
        mma16_ldsm(Ab[b] + 512 * 4, Bb[b] + 2048 * 4, aoff, boff, acc);
    }
    __syncthreads();   // pipeline reads done before aliasing dyn as vt

#pragma unroll
    for (int mt = 0; mt < 2; mt++)
#pragma unroll
        for (int half = 0; half < 2; half++) {
            const int c = wm * 32 + mt * 16 + g + half * 8;
            const float bias = b_in[wrow + c];
#pragma unroll
            for (int nt = 0; nt < 8; nt++) {
                const int t = wn * 64 + nt * 8 + ltg * 2;
                __half2 hv = __floats2half2_rn(
                    acc[mt][nt][half * 2 + 0] + bias,
                    acc[mt][nt][half * 2 + 1] + bias);
                *(__half2*)&vt[c * 264 + t] = hv;
            }
        }
    __syncthreads();

    __half* vb = g_vt16 + ((size_t)(n * Ss + s) * KF) * Tt;
    for (int idx = tid; idx < 64 * 128; idx += 256) {
        const int c = idx >> 7, w = idx & 127;
        const uint32_t val = *(const uint32_t*)&vt[c * 264 + w * 2];
        ((uint32_t*)(vb + (size_t)(c * 25 + v) * Tt))[w] = val;
    }
}

// ---------------------------------------------------------------------------
// Kernel 2: att = tanh(Q K^T / 1600). fp16 MMA + ldmatrix, fp16 output.
// ---------------------------------------------------------------------------
__global__ __launch_bounds__(256, 2) void k_att() {
    extern __shared__ __align__(16) uint32_t dyn[];
    uint32_t* AsP = dyn;
    uint32_t* BsP = dyn + 3 * 1024;
    const int ns = blockIdx.z;
    const int n = ns / 3, s = ns - 3 * n;
    const int t0 = blockIdx.y * 64;
    const int tid = threadIdx.x, warp = tid >> 5, lane = tid & 31;
    const int wm = warp >> 2, wn = warp & 3;
    const int g = lane >> 2, ltg = lane & 3;

    const __half* Qb = g_qk + (((size_t)(n * 2 + 0) * Ss + s) * Tt) * KF;
    const __half* Kb = g_qk + (((size_t)(n * 2 + 1) * Ss + s) * Tt) * KF;

    const int r2 = tid >> 1, au = tid & 1;

    uint32_t aoff[2], boff[4];
    frag_offsets(wm * 32, wn * 64, lane, aoff, boff);
    uint32_t Ab[3], Bb[3];
#pragma unroll
    for (int s2 = 0; s2 < 3; s2++) {
        Ab[s2] = smem_u32(AsP + s2 * 1024);
        Bb[s2] = smem_u32(BsP + s2 * 4096);
    }

    auto stagepair = [&](int buf, int c2) {
        uint32_t* A0 = AsP + buf * 1024;
        uint32_t* B0 = BsP + buf * 4096;
#pragma unroll
        for (int sub = 0; sub < 2; sub++) {
            const int k0 = c2 * 32 + sub * 16;
            if (tid < 128)
                cp16(smem_u32(A0 + sub * 512 + sw_off(r2, au)),
                     Qb + (size_t)(t0 + r2) * KF + k0 + au * 8);
#pragma unroll
            for (int i = 0; i < 2; i++) {
                const int q = r2 + 128 * i;
                cp16(smem_u32(B0 + sub * 2048 + sw_off(q, au)),
                     Kb + (size_t)q * KF + k0 + au * 8);
            }
        }
    };

    float acc[2][8][4] = {};
    const int NP = KF / 32;   // 50
    stagepair(0, 0); CP_COMMIT();
    stagepair(1, 1); CP_COMMIT();
#pragma unroll 1
    for (int c2 = 0; c2 < NP; c2++) {
        CP_WAITG1();
        __syncthreads();
        if (c2 + 2 < NP) stagepair((c2 + 2) % 3, c2 + 2);
        CP_COMMIT();
        const int b = c2 % 3;
        mma16_ldsm(Ab[b],           Bb[b],            aoff, boff, acc);
        mma16_ldsm(Ab[b] + 512 * 4, Bb[b] + 2048 * 4, aoff, boff, acc);
    }

    const float scale = 1.0f / (float)KF;
    __half* arow = g_att16 + (size_t)ns * Tt * Tt;
#pragma unroll
    for (int mt = 0; mt < 2; mt++)
#pragma unroll
        for (int half = 0; half < 2; half++) {
            const int t = t0 + wm * 32 + mt * 16 + g + half * 8;
#pragma unroll
            for (int nt = 0; nt < 8; nt++) {
                const int q = wn * 64 + nt * 8 + ltg * 2;
                __half2 o = __floats2half2_rn(
                    tanhf(acc[mt][nt][half * 2 + 0] * scale),
                    tanhf(acc[mt][nt][half * 2 + 1] * scale));
                *(__half2*)&arow[(size_t)t * Tt + q] = o;
            }
        }
}

// ---------------------------------------------------------------------------
// Kernel 3: y = att @ V, one block per (n,s,v). fp16 MMA + ldmatrix.
// M=256(t, 8 warps), N=64(c), K=256(q). Epilogue: y^T fp16 [p][d].
// ---------------------------------------------------------------------------
__global__ __launch_bounds__(256, 2) void k_y() {
    extern __shared__ __align__(16) uint32_t dyn[];
    uint32_t* AsP = dyn;            // 3 x 4096 (pair = 2 x 2048)
    uint32_t* BsP = dyn + 3 * 4096; // 3 x 1024 (pair = 2 x 512)
    const int v  = blockIdx.x;    // 0..24
    const int ns = blockIdx.z;
    const int n = ns / 3, s = ns - 3 * n;
    const int tid = threadIdx.x, warp = tid >> 5, lane = tid & 31;
    const int g = lane >> 2, ltg = lane & 3;

    const __half* att = g_att16 + (size_t)ns * Tt * Tt;
    const __half* Vb  = g_vt16 + ((size_t)(n * Ss + s) * KF) * Tt;

    const int r2 = tid >> 1, au = tid & 1;

    uint32_t aoff[2], boff[4];
    frag_offsets(warp * 32, 0, lane, aoff, boff);
    uint32_t Ab[3], Bb[3];
#pragma unroll
    for (int s2 = 0; s2 < 3; s2++) {
        Ab[s2] = smem_u32(AsP + s2 * 4096);
        Bb[s2] = smem_u32(BsP + s2 * 1024);
    }

    auto stagepair = [&](int buf, int c2) {
        uint32_t* A0 = AsP + buf * 4096;
        uint32_t* B0 = BsP + buf * 1024;
#pragma unroll
        for (int sub = 0; sub < 2; sub++) {
            const int k0 = c2 * 32 + sub * 16;
#pragma unroll
            for (int i = 0; i < 2; i++) {
                const int t = r2 + 128 * i;
                cp16(smem_u32(A0 + sub * 2048 + sw_off(t, au)),
                     att + (size_t)t * Tt + k0 + au * 8);
            }
            if (tid < 128)
                cp16(smem_u32(B0 + sub * 512 + sw_off(r2, au)),
                     Vb + (size_t)(r2 * 25 + v) * Tt + k0 + au * 8);
        }
    };

    float acc[2][8][4] = {};
    const int NP = Tt / 32;   // 8
    stagepair(0, 0); CP_COMMIT();
    stagepair(1, 1); CP_COMMIT();
#pragma unroll 1
    for (int c2 = 0; c2 < NP; c2++) {
        CP_WAITG1();
        __syncthreads();
        if (c2 + 2 < NP) stagepair((c2 + 2) % 3, c2 + 2);
        CP_COMMIT();
        const int b = c2 % 3;
        mma16_ldsm(Ab[b],            Bb[b],           aoff, boff, acc);
        mma16_ldsm(Ab[b] + 2048 * 4, Bb[b] + 512 * 4, aoff, boff, acc);
    }

    __half* yt = g_yt16 + (size_t)n * TV * Cc + s * MID;
#pragma unroll
    for (int mt = 0; mt < 2; mt++)
#pragma unroll
        for (int half = 0; half < 2; half++) {
            const int t = warp * 32 + mt * 16 + g + half * 8;
            __half* row = yt + (size_t)(t * 25 + v) * Cc;
#pragma unroll
            for (int nt = 0; nt < 8; nt++) {
                const int c = nt * 8 + ltg * 2;
                __half2 hv = __floats2half2_rn(
                    acc[mt][nt][half * 2 + 0],
                    acc[mt][nt][half * 2 + 1]);
                *(__half2*)&row[c] = hv;
            }
        }
}

// ---------------------------------------------------------------------------
// Kernel 4: FF + BN + residual + LeakyReLU, fp16 MMA + ldmatrix.
// ---------------------------------------------------------------------------
__global__ __launch_bounds__(256, 2) void k_ff(const float* __restrict__ x,
                                               const float* __restrict__ b_ff,
                                               const float* __restrict__ gamma,
                                               const float* __restrict__ beta,
                                               const float* __restrict__ mean,
                                               const float* __restrict__ var,
                                               float* __restrict__ out) {
    extern __shared__ __align__(16) uint32_t dyn[];
    uint32_t* AsP = dyn;
    uint32_t* BsP = dyn + 3 * 1024;
    const int n  = blockIdx.z;
    const int d0 = blockIdx.x * 64;
    const int p0 = blockIdx.y * 256;
    const int tid = threadIdx.x, warp = tid >> 5, lane = tid & 31;
    const int wm = warp >> 2, wn = warp & 3;
    const int g = lane >> 2, ltg = lane & 3;

    const __half* yt = g_yt16 + (size_t)n * TV * Cc;

    const int r2 = tid >> 1, au = tid & 1;

    uint32_t aoff[2], boff[4];
    frag_offsets(wm * 32, wn * 64, lane, aoff, boff);
    uint32_t Ab[3], Bb[3];
#pragma unroll
    for (int s2 = 0; s2 < 3; s2++) {
        Ab[s2] = smem_u32(AsP + s2 * 1024);
        Bb[s2] = smem_u32(BsP + s2 * 4096);
    }

    auto stagepair = [&](int buf, int c2) {
        uint32_t* A0 = AsP + buf * 1024;
        uint32_t* B0 = BsP + buf * 4096;
#pragma unroll
        for (int sub = 0; sub < 2; sub++) {
            const int k0 = c2 * 32 + sub * 16;
            if (tid < 128)
                cp16(smem_u32(A0 + sub * 512 + sw_off(r2, au)),
                     g_wff16 + (size_t)(d0 + r2) * Cc + k0 + au * 8);
#pragma unroll
            for (int i = 0; i < 2; i++) {
                const int p = r2 + 128 * i;
                cp16(smem_u32(B0 + sub * 2048 + sw_off(p, au)),
                     yt + (size_t)(p0 + p) * Cc + k0 + au * 8);
            }
        }
    };

    float acc[2][8][4] = {};
    const int NP = Cc / 32;   // 6
    stagepair(0, 0); CP_COMMIT();
    stagepair(1, 1); CP_COMMIT();
#pragma unroll 1
    for (int c2 = 0; c2 < NP; c2++) {
        CP_WAITG1();
        __syncthreads();
        if (c2 + 2 < NP) stagepair((c2 + 2) % 3, c2 + 2);
        CP_COMMIT();
        const int b = c2 % 3;
        mma16_ldsm(Ab[b],           Bb[b],            aoff, boff, acc);
        mma16_ldsm(Ab[b] + 512 * 4, Bb[b] + 2048 * 4, aoff, boff, acc);
    }

    const float* xn = x + (size_t)n * Cc * TV;
    float* on = out + (size_t)n * Cc * TV;
#pragma unroll
    for (int mt = 0; mt < 2; mt++)
#pragma unroll
        for (int half = 0; half < 2; half++) {
            const int d = d0 + wm * 32 + mt * 16 + g + half * 8;
            const float inv = gamma[d] * rsqrtf(var[d] + 1e-5f);
            const float add = (b_ff[d] - mean[d]) * inv + beta[d];
#pragma unroll
            for (int nt = 0; nt < 8; nt++) {
                const int p = p0 + wn * 64 + nt * 8 + ltg * 2;
                const size_t off = (size_t)d * TV + p;
                float2 xv = *(const float2*)&xn[off];
                float z0 = xv.x + acc[mt][nt][half * 2 + 0] * inv + add;
                float z1 = xv.y + acc[mt][nt][half * 2 + 1] * inv + add;
                float2 o;
                o.x = z0 >= 0.f ? z0 : 0.1f * z0;
                o.y = z1 >= 0.f ? z1 : 0.1f * z1;
                *(float2*)&on[off] = o;
            }
        }
}

// ---------------------------------------------------------------------------
extern "C" void kernel_launch(void* const* d_in, const int* in_sizes, int n_in,
                              void* d_out, int out_size) {
    (void)in_sizes; (void)n_in; (void)out_size;
    const float* x     = (const float*)d_in[0];
    const float* w_in  = (const float*)d_in[1];
    const float* b_in  = (const float*)d_in[2];
    const float* w_ff  = (const float*)d_in[3];
    const float* b_ff  = (const float*)d_in[4];
    const float* gamma = (const float*)d_in[5];
    const float* beta  = (const float*)d_in[6];
    const float* mean  = (const float*)d_in[7];
    const float* var   = (const float*)d_in[8];
    float* out = (float*)d_out;

    const int SM = DYN_B32 * 4;   // 61440 B
    static bool attr_set = false;
    if (!attr_set) {
        cudaFuncSetAttribute(k_qkv, cudaFuncAttributeMaxDynamicSharedMemorySize, SM);
        cudaFuncSetAttribute(k_v,   cudaFuncAttributeMaxDynamicSharedMemorySize, SM);
        cudaFuncSetAttribute(k_att, cudaFuncAttributeMaxDynamicSharedMemorySize, SM);
        cudaFuncSetAttribute(k_y,   cudaFuncAttributeMaxDynamicSharedMemorySize, SM);
        cudaFuncSetAttribute(k_ff,  cudaFuncAttributeMaxDynamicSharedMemorySize, SM);
        attr_set = true;
    }

    k_wcv <<<(C3 * Cc + 255) / 256, 256>>>(w_in, w_ff);
    k_cvtx<<<dim3(TV / 64, Nn), 256>>>(x);
    k_qkv <<<dim3(2 * Cc / 64, TV / 256, Nn), 256, SM>>>(b_in);
    k_v   <<<dim3(Vv, Ss, Nn), 256, SM>>>(b_in);
    k_att <<<dim3(1, Tt / 64, Nn * Ss), 256, SM>>>();
    k_y   <<<dim3(Vv, 1, Nn * Ss), 256, SM>>>();
    k_ff  <<<dim3(Cc / 64, TV / 256, Nn), 256, SM>>>(x, b_ff, gamma, beta,
                                                     mean, var, out);
}

// round 17
// speedup vs baseline: 1.0965x; 1.0054x over previous
#include <cuda_runtime.h>
#include <cuda_fp16.h>
#include <math.h>
#include <stdint.h>

#define Nn   32
#define Cc   192
#define Tt   256
#define Vv   25
#define Ss   3
#define MID  64
#define TV   6400          /* T*V */
#define C3   576           /* 3*C */
#define KF   1600          /* MID*Vv flattened contraction for attention */

// Scratch (static device arrays; allocation-free per harness rules)
__device__ __align__(16) __half g_xt16[(size_t)Nn * TV * Cc];        // x^T fp16 [n][p][c]
__device__ __align__(16) __half g_win16[C3 * Cc];                    // w_in fp16
__device__ __align__(16) __half g_wff16[Cc * Cc];                    // w_ff fp16
__device__ __align__(16) __half g_qk[(size_t)Nn * 2 * Ss * Tt * KF]; // Q,K fp16 [n][part][s][t][kf]
__device__ __align__(16) __half g_vt16[(size_t)Nn * Ss * KF * Tt];   // V^T fp16 [n][s][j][t]
__device__ __align__(16) __half g_att16[(size_t)Nn * Ss * Tt * Tt];  // att fp16 [ns][t][q]
__device__ __align__(16) __half g_yt16[(size_t)Nn * TV * Cc];        // y^T fp16 [n][p][d]

// ---------------------------------------------------------------------------
// helpers
// ---------------------------------------------------------------------------
__device__ __forceinline__ void mma_f16(float* d, const uint32_t* a,
                                        uint32_t b0, uint32_t b1) {
    asm volatile(
        "mma.sync.aligned.m16n8k16.row.col.f32.f16.f16.f32 "
        "{%0,%1,%2,%3}, {%4,%5,%6,%7}, {%8,%9}, {%0,%1,%2,%3};"
        : "+f"(d[0]), "+f"(d[1]), "+f"(d[2]), "+f"(d[3])
        : "r"(a[0]), "r"(a[1]), "r"(a[2]), "r"(a[3]), "r"(b0), "r"(b1));
}
__device__ __forceinline__ void ldsm4(uint32_t* r, uint32_t addr) {
    asm volatile(
        "ldmatrix.sync.aligned.m8n8.x4.shared.b16 {%0,%1,%2,%3}, [%4];"
        : "=r"(r[0]), "=r"(r[1]), "=r"(r[2]), "=r"(r[3]) : "r"(addr));
}
__device__ __forceinline__ uint32_t smem_u32(const void* p) {
    return (uint32_t)__cvta_generic_to_shared(p);
}
__device__ __forceinline__ void cp16(uint32_t dst, const void* src) {
    asm volatile("cp.async.cg.shared.global [%0], [%1], 16;"
                 :: "r"(dst), "l"(src));
}
#define CP_COMMIT() asm volatile("cp.async.commit_group;")
#define CP_WAITG1() asm volatile("cp.async.wait_group 1;" ::: "memory")

// ---------------------------------------------------------------------------
// fp16 tile format (validated R7-R16): [row][16 halves] = 8 b32/row;
// 16B granule u of row r stored at granule (u ^ ((r>>2)&1)).
// Fragment loads via ldmatrix.x4 (verified conflict-free on this layout).
// ---------------------------------------------------------------------------
__device__ __forceinline__ void frag_offsets(int m0, int n0, int lane,
                                             uint32_t aoff[2], uint32_t boff[4]) {
#pragma unroll
    for (int mt = 0; mt < 2; mt++) {
        const int row = m0 + mt * 16 + (lane & 15);
        const int kh = lane >> 4;
        const int gr = kh ^ ((row >> 2) & 1);
        aoff[mt] = (uint32_t)(row * 8 + gr * 4) * 4;
    }
#pragma unroll
    for (int np = 0; np < 4; np++) {
        const int row = n0 + np * 16 + ((lane >> 4) << 3) + (lane & 7);
        const int kh = (lane >> 3) & 1;
        const int gr = kh ^ ((row >> 2) & 1);
        boff[np] = (uint32_t)(row * 8 + gr * 4) * 4;
    }
}

__device__ __forceinline__ void mma16_ldsm(uint32_t Abase, uint32_t Bbase,
                                           const uint32_t* aoff,
                                           const uint32_t* boff,
                                           float acc[2][8][4]) {
    uint32_t a[2][4];
    ldsm4(a[0], Abase + aoff[0]);
    ldsm4(a[1], Abase + aoff[1]);
#pragma unroll
    for (int np = 0; np < 4; np++) {
        uint32_t b4[4];
        ldsm4(b4, Bbase + boff[np]);
        mma_f16(acc[0][2 * np],     a[0], b4[0], b4[1]);
        mma_f16(acc[1][2 * np],     a[1], b4[0], b4[1]);
        mma_f16(acc[0][2 * np + 1], a[0], b4[2], b4[3]);
        mma_f16(acc[1][2 * np + 1], a[1], b4[2], b4[3]);
    }
}

// 32x32 warp-tile variants (k_att): acc[2][4][4], 2 B-ldsm per chunk.
__device__ __forceinline__ void frag_offsets2(int m0, int n0, int lane,
                                              uint32_t aoff[2], uint32_t boff[2]) {
#pragma unroll
    for (int mt = 0; mt < 2; mt++) {
        const int row = m0 + mt * 16 + (lane & 15);
        const int kh = lane >> 4;
        const int gr = kh ^ ((row >> 2) & 1);
        aoff[mt] = (uint32_t)(row * 8 + gr * 4) * 4;
    }
#pragma unroll
    for (int np = 0; np < 2; np++) {
        const int row = n0 + np * 16 + ((lane >> 4) << 3) + (lane & 7);
        const int kh = (lane >> 3) & 1;
        const int gr = kh ^ ((row >> 2) & 1);
        boff[np] = (uint32_t)(row * 8 + gr * 4) * 4;
    }
}

__device__ __forceinline__ void mma16_ldsm2(uint32_t Abase, uint32_t Bbase,
                                            const uint32_t* aoff,
                                            const uint32_t* boff,
                                            float acc[2][4][4]) {
    uint32_t a[2][4];
    ldsm4(a[0], Abase + aoff[0]);
    ldsm4(a[1], Abase + aoff[1]);
#pragma unroll
    for (int np = 0; np < 2; np++) {
        uint32_t b4[4];
        ldsm4(b4, Bbase + boff[np]);
        mma_f16(acc[0][2 * np],     a[0], b4[0], b4[1]);
        mma_f16(acc[1][2 * np],     a[1], b4[0], b4[1]);
        mma_f16(acc[0][2 * np + 1], a[0], b4[2], b4[3]);
        mma_f16(acc[1][2 * np + 1], a[1], b4[2], b4[3]);
    }
}

__device__ __forceinline__ int sw_off(int r, int au) {
    return r * 8 + (au ^ ((r >> 2) & 1)) * 4;
}

// Pair-buffer geometry: 3 pipeline slots x two BK=16 chunks.
#define DYN_B32 15360     /* 3 * (1024 + 4096) = 61440 B (64-wide kernels) */
#define ATT_B32 9216      /* 3 * (1024 + 2048) = 36864 B (k_att) */

// ---------------------------------------------------------------------------
// Kernel 0a: weights -> fp16.
// ---------------------------------------------------------------------------
__global__ void k_wcv(const float* __restrict__ w_in,
                      const float* __restrict__ w_ff) {
    const int i = blockIdx.x * 256 + threadIdx.x;
    if (i < C3 * Cc) g_win16[i] = __float2half(w_in[i]);
    if (i < Cc * Cc) g_wff16[i] = __float2half(w_ff[i]);
}

// ---------------------------------------------------------------------------
// Kernel 0b: transpose-convert x [n][c][p] fp32 -> xt16 [n][p][c] fp16.
// ---------------------------------------------------------------------------
__global__ __launch_bounds__(256) void k_cvtx(const float* __restrict__ x) {
    __shared__ uint32_t sm[64 * 97];
    const int n = blockIdx.y, p0 = blockIdx.x * 64;
    const float* xn = x + (size_t)n * Cc * TV;
    for (int idx = threadIdx.x; idx < 96 * 64; idx += 256) {
        const int c2 = idx >> 6, p = idx & 63;
        const float f0 = xn[(size_t)(2 * c2) * TV + p0 + p];
        const float f1 = xn[(size_t)(2 * c2 + 1) * TV + p0 + p];
        const __half2 h = __floats2half2_rn(f0, f1);
        sm[p * 97 + c2] = *(const uint32_t*)&h;
    }
    __syncthreads();
    uint32_t* dst = (uint32_t*)g_xt16 + ((size_t)n * TV + p0) * (Cc / 2);
    for (int idx = threadIdx.x; idx < 64 * 96; idx += 256) {
        const int p = idx / 96, u = idx - p * 96;
        dst[(size_t)p * 96 + u] = sm[p * 97 + u];
    }
}

// ---------------------------------------------------------------------------
// Kernel 1: Q,K projection (fp16 MMA + ldmatrix). Block 64(d) x 256(p), K=192.
// ---------------------------------------------------------------------------
__global__ __launch_bounds__(256, 2) void k_qkv(const float* __restrict__ b_in) {
    extern __shared__ __align__(16) uint32_t dyn[];
    uint32_t* AsP = dyn;            // 3 x 1024 (pair = 2 x 512)
    uint32_t* BsP = dyn + 3 * 1024; // 3 x 4096 (pair = 2 x 2048)
    const int n  = blockIdx.z;
    const int d0 = blockIdx.x * 64;      // 0..320 (Q,K only)
    const int p0 = blockIdx.y * 256;
    const int tid = threadIdx.x, warp = tid >> 5, lane = tid & 31;
    const int wm = warp >> 2, wn = warp & 3;
    const int g = lane >> 2, ltg = lane & 3;

    const int r2 = tid >> 1, au = tid & 1;

    uint32_t aoff[2], boff[4];
    frag_offsets(wm * 32, wn * 64, lane, aoff, boff);
    uint32_t Ab[3], Bb[3];
#pragma unroll
    for (int s2 = 0; s2 < 3; s2++) {
        Ab[s2] = smem_u32(AsP + s2 * 1024);
        Bb[s2] = smem_u32(BsP + s2 * 4096);
    }

    auto stagepair = [&](int buf, int c2) {
        uint32_t* A0 = AsP + buf * 1024;
        uint32_t* B0 = BsP + buf * 4096;
#pragma unroll
        for (int sub = 0; sub < 2; sub++) {
            const int k0 = c2 * 32 + sub * 16;
            if (tid < 128)
                cp16(smem_u32(A0 + sub * 512 + sw_off(r2, au)),
                     g_win16 + (size_t)(d0 + r2) * Cc + k0 + au * 8);
#pragma unroll
            for (int i = 0; i < 2; i++) {
                const int p = r2 + 128 * i;
                cp16(smem_u32(B0 + sub * 2048 + sw_off(p, au)),
                     g_xt16 + ((size_t)n * TV + p0 + p) * Cc + k0 + au * 8);
            }
        }
    };

    float acc[2][8][4] = {};
    const int NP = Cc / 32;   // 6
    stagepair(0, 0); CP_COMMIT();
    stagepair(1, 1); CP_COMMIT();
#pragma unroll 1
    for (int c2 = 0; c2 < NP; c2++) {
        CP_WAITG1();
        __syncthreads();
        if (c2 + 2 < NP) stagepair((c2 + 2) % 3, c2 + 2);
        CP_COMMIT();
        const int b = c2 % 3;
        mma16_ldsm(Ab[b],            Bb[b],            aoff, boff, acc);
        mma16_ldsm(Ab[b] + 512 * 4,  Bb[b] + 2048 * 4, aoff, boff, acc);
    }

    const int part = d0 / Cc;           // 0=Q, 1=K
    const int s = (d0 % Cc) / MID;
    __half* qk = g_qk + (((size_t)(n * 2 + part) * Ss + s) * Tt) * KF;
#pragma unroll
    for (int mt = 0; mt < 2; mt++)
#pragma unroll
        for (int half = 0; half < 2; half++) {
            const int cch = wm * 32 + mt * 16 + g + half * 8;
            const float bias = b_in[d0 + cch];
#pragma unroll
            for (int nt = 0; nt < 8; nt++)
#pragma unroll
                for (int e = 0; e < 2; e++) {
                    const int p = p0 + wn * 64 + nt * 8 + ltg * 2 + e;
                    const int t = p / 25, v = p - t * 25;
                    qk[(size_t)t * KF + cch * 25 + v] =
                        __float2half(acc[mt][nt][half * 2 + e] + bias);
                }
        }
}

// ---------------------------------------------------------------------------
// Kernel 1b: V projection -> V^T fp16 [j][t], coalesced. ldmatrix fragments.
// ---------------------------------------------------------------------------
__global__ __launch_bounds__(256, 2) void k_v(const float* __restrict__ b_in) {
    extern __shared__ __align__(16) uint32_t dyn[];
    uint32_t* AsP = dyn;
    uint32_t* BsP = dyn + 3 * 1024;
    __half*  vt  = (__half*)dyn;    // epilogue alias (64 x 264 halves = 33 KB)
    const int v = blockIdx.x;     // 0..24
    const int s = blockIdx.y;     // 0..2
    const int n = blockIdx.z;
    const int tid = threadIdx.x, warp = tid >> 5, lane = tid & 31;
    const int wm = warp >> 2, wn = warp & 3;
    const int g = lane >> 2, ltg = lane & 3;

    const int wrow = 2 * Cc + s * MID;
    const __half* Wv = g_win16 + (size_t)wrow * Cc;
    const __half* Xt = g_xt16 + (size_t)n * TV * Cc;

    const int r2 = tid >> 1, au = tid & 1;

    uint32_t aoff[2], boff[4];
    frag_offsets(wm * 32, wn * 64, lane, aoff, boff);
    uint32_t Ab[3], Bb[3];
#pragma unroll
    for (int s2 = 0; s2 < 3; s2++) {
        Ab[s2] = smem_u32(AsP + s2 * 1024);
        Bb[s2] = smem_u32(BsP + s2 * 4096);
    }

    auto stagepair = [&](int buf, int c2) {
        uint32_t* A0 = AsP + buf * 1024;
        uint32_t* B0 = BsP + buf * 4096;
#pragma unroll
        for (int sub = 0; sub < 2; sub++) {
            const int k0 = c2 * 32 + sub * 16;
            if (tid < 128)
                cp16(smem_u32(A0 + sub * 512 + sw_off(r2, au)),
                     Wv + (size_t)r2 * Cc + k0 + au * 8);
#pragma unroll
            for (int i = 0; i < 2; i++) {
                const int t = r2 + 128 * i;
                cp16(smem_u32(B0 + sub * 2048 + sw_off(t, au)),
                     Xt + (size_t)(25 * t + v) * Cc + k0 + au * 8);
            }
        }
    };

    float acc[2][8][4] = {};
    const int NP = Cc / 32;   // 6
    stagepair(0, 0); CP_COMMIT();
    stagepair(1, 1); CP_COMMIT();
#pragma unroll 1
    for (int c2 = 0; c2 < NP; c2++) {
        CP_WAITG1();
        __syncthreads();
        if (c2 + 2 < NP) stagepair((c2 + 2) % 3, c2 + 2);
        CP_COMMIT();
        const int b = c2 % 3;
        mma16_ldsm(Ab[b],           Bb[b],            aoff, boff, acc);
        mma16_ldsm(Ab[b] + 512 * 4, Bb[b] + 2048 * 4, aoff, boff, acc);
    }
    __syncthreads();   // pipeline reads done before aliasing dyn as vt

#pragma unroll
    for (int mt = 0; mt < 2; mt++)
#pragma unroll
        for (int half = 0; half < 2; half++) {
            const int c = wm * 32 + mt * 16 + g + half * 8;
            const float bias = b_in[wrow + c];
#pragma unroll
            for (int nt = 0; nt < 8; nt++) {
                const int t = wn * 64 + nt * 8 + ltg * 2;
                __half2 hv = __floats2half2_rn(
                    acc[mt][nt][half * 2 + 0] + bias,
                    acc[mt][nt][half * 2 + 1] + bias);
                *(__half2*)&vt[c * 264 + t] = hv;
            }
        }
    __syncthreads();

    __half* vb = g_vt16 + ((size_t)(n * Ss + s) * KF) * Tt;
    for (int idx = tid; idx < 64 * 128; idx += 256) {
        const int c = idx >> 7, w = idx & 127;
        const uint32_t val = *(const uint32_t*)&vt[c * 264 + w * 2];
        ((uint32_t*)(vb + (size_t)(c * 25 + v) * Tt))[w] = val;
    }
}

// ---------------------------------------------------------------------------
// Kernel 2: att = tanh(Q K^T / 1600). fp16 MMA + ldmatrix, fp16 output.
// Tile 64(t) x 128(q) -> grid (2,4,96)=768 blocks (wave-quantization fix).
// Warp tile 32x32, acc=32 floats -> 3 CTAs/SM.
// ---------------------------------------------------------------------------
__global__ __launch_bounds__(256, 3) void k_att() {
    extern __shared__ __align__(16) uint32_t dyn[];
    uint32_t* AsP = dyn;            // 3 x 1024 (pair = 2 x 512)
    uint32_t* BsP = dyn + 3 * 1024; // 3 x 2048 (pair = 2 x 1024)
    const int ns = blockIdx.z;
    const int n = ns / 3, s = ns - 3 * n;
    const int q0 = blockIdx.x * 128;
    const int t0 = blockIdx.y * 64;
    const int tid = threadIdx.x, warp = tid >> 5, lane = tid & 31;
    const int wm = warp >> 2, wn = warp & 3;
    const int g = lane >> 2, ltg = lane & 3;

    const __half* Qb = g_qk + (((size_t)(n * 2 + 0) * Ss + s) * Tt) * KF;
    const __half* Kb = g_qk + (((size_t)(n * 2 + 1) * Ss + s) * Tt) * KF;

    const int r2 = tid >> 1, au = tid & 1;

    uint32_t aoff[2], boff[2];
    frag_offsets2(wm * 32, wn * 32, lane, aoff, boff);
    uint32_t Ab[3], Bb[3];
#pragma unroll
    for (int s2 = 0; s2 < 3; s2++) {
        Ab[s2] = smem_u32(AsP + s2 * 1024);
        Bb[s2] = smem_u32(BsP + s2 * 2048);
    }

    auto stagepair = [&](int buf, int c2) {
        uint32_t* A0 = AsP + buf * 1024;
        uint32_t* B0 = BsP + buf * 2048;
#pragma unroll
        for (int sub = 0; sub < 2; sub++) {
            const int k0 = c2 * 32 + sub * 16;
            if (tid < 128)
                cp16(smem_u32(A0 + sub * 512 + sw_off(r2, au)),
                     Qb + (size_t)(t0 + r2) * KF + k0 + au * 8);
            cp16(smem_u32(B0 + sub * 1024 + sw_off(r2, au)),
                 Kb + (size_t)(q0 + r2) * KF + k0 + au * 8);
        }
    };

    float acc[2][4][4] = {};
    const int NP = KF / 32;   // 50
    stagepair(0, 0); CP_COMMIT();
    stagepair(1, 1); CP_COMMIT();
#pragma unroll 1
    for (int c2 = 0; c2 < NP; c2++) {
        CP_WAITG1();
        __syncthreads();
        if (c2 + 2 < NP) stagepair((c2 + 2) % 3, c2 + 2);
        CP_COMMIT();
        const int b = c2 % 3;
        mma16_ldsm2(Ab[b],           Bb[b],            aoff, boff, acc);
        mma16_ldsm2(Ab[b] + 512 * 4, Bb[b] + 1024 * 4, aoff, boff, acc);
    }

    const float scale = 1.0f / (float)KF;
    __half* arow = g_att16 + (size_t)ns * Tt * Tt;
#pragma unroll
    for (int mt = 0; mt < 2; mt++)
#pragma unroll
        for (int half = 0; half < 2; half++) {
            const int t = t0 + wm * 32 + mt * 16 + g + half * 8;
#pragma unroll
            for (int nt = 0; nt < 4; nt++) {
                const int q = q0 + wn * 32 + nt * 8 + ltg * 2;
                __half2 o = __floats2half2_rn(
                    tanhf(acc[mt][nt][half * 2 + 0] * scale),
                    tanhf(acc[mt][nt][half * 2 + 1] * scale));
                *(__half2*)&arow[(size_t)t * Tt + q] = o;
            }
        }
}

// ---------------------------------------------------------------------------
// Kernel 3: y = att @ V, one block per (n,s,v). fp16 MMA + ldmatrix.
// M=256(t, 8 warps), N=64(c), K=256(q). Epilogue: y^T fp16 [p][d].
// ---------------------------------------------------------------------------
__global__ __launch_bounds__(256, 2) void k_y() {
    extern __shared__ __align__(16) uint32_t dyn[];
    uint32_t* AsP = dyn;            // 3 x 4096 (pair = 2 x 2048)
    uint32_t* BsP = dyn + 3 * 4096; // 3 x 1024 (pair = 2 x 512)
    const int v  = blockIdx.x;    // 0..24
    const int ns = blockIdx.z;
    const int n = ns / 3, s = ns - 3 * n;
    const int tid = threadIdx.x, warp = tid >> 5, lane = tid & 31;
    const int g = lane >> 2, ltg = lane & 3;

    const __half* att = g_att16 + (size_t)ns * Tt * Tt;
    const __half* Vb  = g_vt16 + ((size_t)(n * Ss + s) * KF) * Tt;

    const int r2 = tid >> 1, au = tid & 1;

    uint32_t aoff[2], boff[4];
    frag_offsets(warp * 32, 0, lane, aoff, boff);
    uint32_t Ab[3], Bb[3];
#pragma unroll
    for (int s2 = 0; s2 < 3; s2++) {
        Ab[s2] = smem_u32(AsP + s2 * 4096);
        Bb[s2] = smem_u32(BsP + s2 * 1024);
    }

    auto stagepair = [&](int buf, int c2) {
        uint32_t* A0 = AsP + buf * 4096;
        uint32_t* B0 = BsP + buf * 1024;
#pragma unroll
        for (int sub = 0; sub < 2; sub++) {
            const int k0 = c2 * 32 + sub * 16;
#pragma unroll
            for (int i = 0; i < 2; i++) {
                const int t = r2 + 128 * i;
                cp16(smem_u32(A0 + sub * 2048 + sw_off(t, au)),
                     att + (size_t)t * Tt + k0 + au * 8);
            }
            if (tid < 128)
                cp16(smem_u32(B0 + sub * 512 + sw_off(r2, au)),
                     Vb + (size_t)(r2 * 25 + v) * Tt + k0 + au * 8);
        }
    };

    float acc[2][8][4] = {};
    const int NP = Tt / 32;   // 8
    stagepair(0, 0); CP_COMMIT();
    stagepair(1, 1); CP_COMMIT();
#pragma unroll 1
    for (int c2 = 0; c2 < NP; c2++) {
        CP_WAITG1();
        __syncthreads();
        if (c2 + 2 < NP) stagepair((c2 + 2) % 3, c2 + 2);
        CP_COMMIT();
        const int b = c2 % 3;
        mma16_ldsm(Ab[b],            Bb[b],           aoff, boff, acc);
        mma16_ldsm(Ab[b] + 2048 * 4, Bb[b] + 512 * 4, aoff, boff, acc);
    }

    __half* yt = g_yt16 + (size_t)n * TV * Cc + s * MID;
#pragma unroll
    for (int mt = 0; mt < 2; mt++)
#pragma unroll
        for (int half = 0; half < 2; half++) {
            const int t = warp * 32 + mt * 16 + g + half * 8;
            __half* row = yt + (size_t)(t * 25 + v) * Cc;
#pragma unroll
            for (int nt = 0; nt < 8; nt++) {
                const int c = nt * 8 + ltg * 2;
                __half2 hv = __floats2half2_rn(
                    acc[mt][nt][half * 2 + 0],
                    acc[mt][nt][half * 2 + 1]);
                *(__half2*)&row[c] = hv;
            }
        }
}

// ---------------------------------------------------------------------------
// Kernel 4: FF + BN + residual + LeakyReLU, fp16 MMA + ldmatrix.
// ---------------------------------------------------------------------------
__global__ __launch_bounds__(256, 2) void k_ff(const float* __restrict__ x,
                                               const float* __restrict__ b_ff,
                                               const float* __restrict__ gamma,
                                               const float* __restrict__ beta,
                                               const float* __restrict__ mean,
                                               const float* __restrict__ var,
                                               float* __restrict__ out) {
    extern __shared__ __align__(16) uint32_t dyn[];
    uint32_t* AsP = dyn;
    uint32_t* BsP = dyn + 3 * 1024;
    const int n  = blockIdx.z;
    const int d0 = blockIdx.x * 64;
    const int p0 = blockIdx.y * 256;
    const int tid = threadIdx.x, warp = tid >> 5, lane = tid & 31;
    const int wm = warp >> 2, wn = warp & 3;
    const int g = lane >> 2, ltg = lane & 3;

    const __half* yt = g_yt16 + (size_t)n * TV * Cc;

    const int r2 = tid >> 1, au = tid & 1;

    uint32_t aoff[2], boff[4];
    frag_offsets(wm * 32, wn * 64, lane, aoff, boff);
    uint32_t Ab[3], Bb[3];
#pragma unroll
    for (int s2 = 0; s2 < 3; s2++) {
        Ab[s2] = smem_u32(AsP + s2 * 1024);
        Bb[s2] = smem_u32(BsP + s2 * 4096);
    }

    auto stagepair = [&](int buf, int c2) {
        uint32_t* A0 = AsP + buf * 1024;
        uint32_t* B0 = BsP + buf * 4096;
#pragma unroll
        for (int sub = 0; sub < 2; sub++) {
            const int k0 = c2 * 32 + sub * 16;
            if (tid < 128)
                cp16(smem_u32(A0 + sub * 512 + sw_off(r2, au)),
                     g_wff16 + (size_t)(d0 + r2) * Cc + k0 + au * 8);
#pragma unroll
            for (int i = 0; i < 2; i++) {
                const int p = r2 + 128 * i;
                cp16(smem_u32(B0 + sub * 2048 + sw_off(p, au)),
                     yt + (size_t)(p0 + p) * Cc + k0 + au * 8);
            }
        }
    };

    float acc[2][8][4] = {};
    const int NP = Cc / 32;   // 6
    stagepair(0, 0); CP_COMMIT();
    stagepair(1, 1); CP_COMMIT();
#pragma unroll 1
    for (int c2 = 0; c2 < NP; c2++) {
        CP_WAITG1();
        __syncthreads();
        if (c2 + 2 < NP) stagepair((c2 + 2) % 3, c2 + 2);
        CP_COMMIT();
        const int b = c2 % 3;
        mma16_ldsm(Ab[b],           Bb[b],            aoff, boff, acc);
        mma16_ldsm(Ab[b] + 512 * 4, Bb[b] + 2048 * 4, aoff, boff, acc);
    }

    const float* xn = x + (size_t)n * Cc * TV;
    float* on = out + (size_t)n * Cc * TV;
#pragma unroll
    for (int mt = 0; mt < 2; mt++)
#pragma unroll
        for (int half = 0; half < 2; half++) {
            const int d = d0 + wm * 32 + mt * 16 + g + half * 8;
            const float inv = gamma[d] * rsqrtf(var[d] + 1e-5f);
            const float add = (b_ff[d] - mean[d]) * inv + beta[d];
#pragma unroll
            for (int nt = 0; nt < 8; nt++) {
                const int p = p0 + wn * 64 + nt * 8 + ltg * 2;
                const size_t off = (size_t)d * TV + p;
                float2 xv = *(const float2*)&xn[off];
                float z0 = xv.x + acc[mt][nt][half * 2 + 0] * inv + add;
                float z1 = xv.y + acc[mt][nt][half * 2 + 1] * inv + add;
                float2 o;
                o.x = z0 >= 0.f ? z0 : 0.1f * z0;
                o.y = z1 >= 0.f ? z1 : 0.1f * z1;
                *(float2*)&on[off] = o;
            }
        }
}

// ---------------------------------------------------------------------------
extern "C" void kernel_launch(void* const* d_in, const int* in_sizes, int n_in,
                              void* d_out, int out_size) {
    (void)in_sizes; (void)n_in; (void)out_size;
    const float* x     = (const float*)d_in[0];
    const float* w_in  = (const float*)d_in[1];
    const float* b_in  = (const float*)d_in[2];
    const float* w_ff  = (const float*)d_in[3];
    const float* b_ff  = (const float*)d_in[4];
    const float* gamma = (const float*)d_in[5];
    const float* beta  = (const float*)d_in[6];
    const float* mean  = (const float*)d_in[7];
    const float* var   = (const float*)d_in[8];
    float* out = (float*)d_out;

    const int SM  = DYN_B32 * 4;   // 61440 B
    const int SMA = ATT_B32 * 4;   // 36864 B
    static bool attr_set = false;
    if (!attr_set) {
        cudaFuncSetAttribute(k_qkv, cudaFuncAttributeMaxDynamicSharedMemorySize, SM);
        cudaFuncSetAttribute(k_v,   cudaFuncAttributeMaxDynamicSharedMemorySize, SM);
        cudaFuncSetAttribute(k_att, cudaFuncAttributeMaxDynamicSharedMemorySize, SMA);
        cudaFuncSetAttribute(k_y,   cudaFuncAttributeMaxDynamicSharedMemorySize, SM);
        cudaFuncSetAttribute(k_ff,  cudaFuncAttributeMaxDynamicSharedMemorySize, SM);
        attr_set = true;
    }

    k_wcv <<<(C3 * Cc + 255) / 256, 256>>>(w_in, w_ff);
    k_cvtx<<<dim3(TV / 64, Nn), 256>>>(x);
    k_qkv <<<dim3(2 * Cc / 64, TV / 256, Nn), 256, SM>>>(b_in);
    k_v   <<<dim3(Vv, Ss, Nn), 256, SM>>>(b_in);
    k_att <<<dim3(2, Tt / 64, Nn * Ss), 256, SMA>>>();
    k_y   <<<dim3(Vv, 1, Nn * Ss), 256, SM>>>();
    k_ff  <<<dim3(Cc / 64, TV / 256, Nn), 256, SM>>>(x, b_ff, gamma, beta,
                                                     mean, var, out);
}